// round 1
// baseline (speedup 1.0000x reference)
#include <cuda_runtime.h>
#include <math.h>

#define NTOK 1024   // N*T
#define DIM  512    // D
#define NHEAD 8
#define DKC  128
#define HALF 64
#define EXP  256
#define NE   65536  // E*E
#define KSEL 16

// ---------------- device scratch (allocation-free rule: __device__ globals) --
__device__ float g_qh[NTOK * NHEAD * DKC];         // 4 MB
__device__ float g_s1[NTOK * NHEAD * EXP];         // 8 MB
__device__ float g_s2[NTOK * NHEAD * EXP];         // 8 MB
__device__ float g_P[NE];                          // 256 KB
__device__ float g_S[(size_t)NTOK * NE];           // 268 MB intermediate S'

// ---------------- zero P and out ---------------------------------------------
__global__ void zero_kernel(float* __restrict__ out) {
  int i = blockIdx.x * blockDim.x + threadIdx.x;
  int stride = gridDim.x * blockDim.x;
  for (int j = i; j < NE; j += stride) g_P[j] = 0.f;
  for (int j = i; j < NTOK * DIM; j += stride) out[j] = 0.f;
}

// ---------------- qh = Q @ Wq^T + bq  (M=1024,N=1024,K=512) ------------------
__global__ __launch_bounds__(256) void gemm_qh_kernel(
    const float* __restrict__ A, const float* __restrict__ B,
    const float* __restrict__ bias) {
  __shared__ float As[16][128];
  __shared__ float Bs[16][128];
  int m0 = blockIdx.x * 128, n0 = blockIdx.y * 128;
  int tid = threadIdx.x;
  int tx = tid & 15, ty = tid >> 4;
  int lr = tid >> 2, lc = tid & 3;
  float acc[8][8];
#pragma unroll
  for (int i = 0; i < 8; i++)
#pragma unroll
    for (int j = 0; j < 8; j++) acc[i][j] = 0.f;

  for (int k0 = 0; k0 < 512; k0 += 16) {
#pragma unroll
    for (int half = 0; half < 2; half++) {
      int r = lr + half * 64;
      float4 va = *(const float4*)&A[(size_t)(m0 + r) * 512 + k0 + lc * 4];
      As[lc * 4 + 0][r] = va.x; As[lc * 4 + 1][r] = va.y;
      As[lc * 4 + 2][r] = va.z; As[lc * 4 + 3][r] = va.w;
      float4 vb = *(const float4*)&B[(size_t)(n0 + r) * 512 + k0 + lc * 4];
      Bs[lc * 4 + 0][r] = vb.x; Bs[lc * 4 + 1][r] = vb.y;
      Bs[lc * 4 + 2][r] = vb.z; Bs[lc * 4 + 3][r] = vb.w;
    }
    __syncthreads();
#pragma unroll
    for (int k = 0; k < 16; k++) {
      float a[8], b[8];
      *(float4*)&a[0] = *(const float4*)&As[k][ty * 8];
      *(float4*)&a[4] = *(const float4*)&As[k][ty * 8 + 4];
      *(float4*)&b[0] = *(const float4*)&Bs[k][tx * 8];
      *(float4*)&b[4] = *(const float4*)&Bs[k][tx * 8 + 4];
#pragma unroll
      for (int i = 0; i < 8; i++)
#pragma unroll
        for (int j = 0; j < 8; j++) acc[i][j] += a[i] * b[j];
    }
    __syncthreads();
  }
#pragma unroll
  for (int i = 0; i < 8; i++) {
    int m = m0 + ty * 8 + i;
#pragma unroll
    for (int j = 0; j < 8; j++) {
      int n = n0 + tx * 8 + j;
      g_qh[(size_t)m * 1024 + n] = acc[i][j] + bias[n];
    }
  }
}

// ---------------- s1/s2 scores per (token, head) ------------------------------
// s1[nt,h,e] = sum_c q1[c]*keys[h,0,e,c]; s2 with half=1.
__global__ __launch_bounds__(256) void scores_kernel(const float* __restrict__ keys) {
  int nt = blockIdx.x, h = blockIdx.y;
  __shared__ float q[128];
  __shared__ float ks[64 * 65];
  int tid = threadIdx.x;
  if (tid < 128) q[tid] = g_qh[((size_t)nt * NHEAD + h) * DKC + tid];
  __syncthreads();
  for (int half = 0; half < 2; half++) {
    const float* qhp = q + half * 64;
    float* dst = (half == 0) ? g_s1 : g_s2;
    for (int et = 0; et < 4; et++) {
      const float* kp = keys + ((size_t)(h * 2 + half) * 256 + et * 64) * 64;
      for (int idx = tid; idx < 4096; idx += 256) {
        int r = idx >> 6, c = idx & 63;
        ks[r * 65 + c] = kp[idx];
      }
      __syncthreads();
      int el = tid >> 2, qq = tid & 3;
      float sum = 0.f;
#pragma unroll
      for (int c = 0; c < 16; c++)
        sum += qhp[qq * 16 + c] * ks[el * 65 + qq * 16 + c];
      sum += __shfl_xor_sync(0xffffffffu, sum, 1);
      sum += __shfl_xor_sync(0xffffffffu, sum, 2);
      if (qq == 0)
        dst[((size_t)nt * NHEAD + h) * EXP + et * 64 + el] = sum;
      __syncthreads();
    }
  }
}

// ---------------- top-k machinery --------------------------------------------
__device__ __forceinline__ void top16_block(float* x, float* rv, int* ri,
                                            float* tv, int* ti, int tid) {
  for (int k = 0; k < KSEL; k++) {
    rv[tid] = x[tid]; ri[tid] = tid;
    __syncthreads();
#pragma unroll
    for (int s = 128; s >= 1; s >>= 1) {
      if (tid < s) {
        float v2 = rv[tid + s];
        int i2 = ri[tid + s];
        if (v2 > rv[tid] || (v2 == rv[tid] && i2 < ri[tid])) {
          rv[tid] = v2; ri[tid] = i2;
        }
      }
      __syncthreads();
    }
    if (tid == 0) {
      tv[k] = rv[0]; ti[k] = ri[0];
      x[ri[0]] = -INFINITY;
    }
    __syncthreads();
  }
}

// one block per (nt, h) row: top16(s1), top16(s2), top16 of 256 combos,
// softmax over the 16, scatter-add probs into g_P.
__global__ __launch_bounds__(256) void topk_kernel() {
  int row = blockIdx.x;           // nt*8 + h
  int tid = threadIdx.x;
  __shared__ float x[256];
  __shared__ float rv[256];
  __shared__ int   ri[256];
  __shared__ float s1v[16], s2v[16], cv[16];
  __shared__ int   s1i[16], s2i[16], ci[16];

  x[tid] = g_s1[(size_t)row * EXP + tid];
  __syncthreads();
  top16_block(x, rv, ri, s1v, s1i, tid);

  x[tid] = g_s2[(size_t)row * EXP + tid];
  __syncthreads();
  top16_block(x, rv, ri, s2v, s2i, tid);

  x[tid] = s1v[tid >> 4] + s2v[tid & 15];
  __syncthreads();
  top16_block(x, rv, ri, cv, ci, tid);

  if (tid == 0) {
    float m = cv[0];                    // descending order -> cv[0] is max
    float p[16];
    float sum = 0.f;
#pragma unroll
    for (int k = 0; k < KSEL; k++) { p[k] = expf(cv[k] - m); sum += p[k]; }
    float inv = 1.0f / sum;
#pragma unroll
    for (int k = 0; k < KSEL; k++) {
      int t = ci[k];
      int idx = s1i[t >> 4] * EXP + s2i[t & 15];
      atomicAdd(&g_P[idx], p[k] * inv);
    }
  }
}

// ---------------- D1: S' = relu(Q @ Wd^T) * P   (M=1024,N=65536,K=512) -------
__global__ __launch_bounds__(256) void gemm_s_kernel(
    const float* __restrict__ A, const float* __restrict__ B) {
  __shared__ float As[16][128];
  __shared__ float Bs[16][128];
  int m0 = blockIdx.x * 128;      // x fastest -> 8 m-tiles share B tile in L2
  int n0 = blockIdx.y * 128;
  int tid = threadIdx.x;
  int tx = tid & 15, ty = tid >> 4;
  int lr = tid >> 2, lc = tid & 3;
  float acc[8][8];
#pragma unroll
  for (int i = 0; i < 8; i++)
#pragma unroll
    for (int j = 0; j < 8; j++) acc[i][j] = 0.f;

  for (int k0 = 0; k0 < 512; k0 += 16) {
#pragma unroll
    for (int half = 0; half < 2; half++) {
      int r = lr + half * 64;
      float4 va = *(const float4*)&A[(size_t)(m0 + r) * 512 + k0 + lc * 4];
      As[lc * 4 + 0][r] = va.x; As[lc * 4 + 1][r] = va.y;
      As[lc * 4 + 2][r] = va.z; As[lc * 4 + 3][r] = va.w;
      float4 vb = *(const float4*)&B[(size_t)(n0 + r) * 512 + k0 + lc * 4];
      Bs[lc * 4 + 0][r] = vb.x; Bs[lc * 4 + 1][r] = vb.y;
      Bs[lc * 4 + 2][r] = vb.z; Bs[lc * 4 + 3][r] = vb.w;
    }
    __syncthreads();
#pragma unroll
    for (int k = 0; k < 16; k++) {
      float a[8], b[8];
      *(float4*)&a[0] = *(const float4*)&As[k][ty * 8];
      *(float4*)&a[4] = *(const float4*)&As[k][ty * 8 + 4];
      *(float4*)&b[0] = *(const float4*)&Bs[k][tx * 8];
      *(float4*)&b[4] = *(const float4*)&Bs[k][tx * 8 + 4];
#pragma unroll
      for (int i = 0; i < 8; i++)
#pragma unroll
        for (int j = 0; j < 8; j++) acc[i][j] += a[i] * b[j];
    }
    __syncthreads();
  }
  float pj[8];
#pragma unroll
  for (int j = 0; j < 8; j++) pj[j] = g_P[n0 + tx * 8 + j];
#pragma unroll
  for (int i = 0; i < 8; i++) {
    int m = m0 + ty * 8 + i;
#pragma unroll
    for (int j = 0; j < 8; j++) {
      int n = n0 + tx * 8 + j;
      g_S[(size_t)m * NE + n] = fmaxf(acc[i][j], 0.f) * pj[j];
    }
  }
}

// ---------------- D2: out = S' @ Wu  (M=1024,N=512,K=65536, split-K=32) ------
__global__ __launch_bounds__(256) void gemm_out_kernel(
    const float* __restrict__ B, float* __restrict__ out) {
  __shared__ float As[16][128];
  __shared__ float Bs[16][128];
  int n0 = blockIdx.x * 128;      // x fastest -> 4 n-tiles share S chunk in L2
  int m0 = blockIdx.y * 128;
  int kb = blockIdx.z * 2048;
  int tid = threadIdx.x;
  int tx = tid & 15, ty = tid >> 4;
  int lr = tid >> 2, lc = tid & 3;
  int kr = tid >> 4, nq = tid & 15;
  float acc[8][8];
#pragma unroll
  for (int i = 0; i < 8; i++)
#pragma unroll
    for (int j = 0; j < 8; j++) acc[i][j] = 0.f;

  for (int k0 = 0; k0 < 2048; k0 += 16) {
#pragma unroll
    for (int half = 0; half < 2; half++) {
      int r = lr + half * 64;
      float4 va = *(const float4*)&g_S[(size_t)(m0 + r) * NE + kb + k0 + lc * 4];
      As[lc * 4 + 0][r] = va.x; As[lc * 4 + 1][r] = va.y;
      As[lc * 4 + 2][r] = va.z; As[lc * 4 + 3][r] = va.w;
      // B = Wu is [K][N] with N contiguous: direct (untransposed) tile load
      float4 vb = *(const float4*)&B[(size_t)(kb + k0 + kr) * 512 + n0 + half * 64 + nq * 4];
      *(float4*)&Bs[kr][half * 64 + nq * 4] = vb;
    }
    __syncthreads();
#pragma unroll
    for (int k = 0; k < 16; k++) {
      float a[8], b[8];
      *(float4*)&a[0] = *(const float4*)&As[k][ty * 8];
      *(float4*)&a[4] = *(const float4*)&As[k][ty * 8 + 4];
      *(float4*)&b[0] = *(const float4*)&Bs[k][tx * 8];
      *(float4*)&b[4] = *(const float4*)&Bs[k][tx * 8 + 4];
#pragma unroll
      for (int i = 0; i < 8; i++)
#pragma unroll
        for (int j = 0; j < 8; j++) acc[i][j] += a[i] * b[j];
    }
    __syncthreads();
  }
#pragma unroll
  for (int i = 0; i < 8; i++) {
    int m = m0 + ty * 8 + i;
#pragma unroll
    for (int j = 0; j < 8; j++) {
      int n = n0 + tx * 8 + j;
      atomicAdd(&out[(size_t)m * DIM + n], acc[i][j]);
    }
  }
}

// ---------------- launch ------------------------------------------------------
extern "C" void kernel_launch(void* const* d_in, const int* in_sizes, int n_in,
                              void* d_out, int out_size) {
  const float* queries = (const float*)d_in[0];   // (2,512,512)
  const float* Wq      = (const float*)d_in[1];   // (1024,512)
  const float* bq      = (const float*)d_in[2];   // (1024)
  const float* keys    = (const float*)d_in[3];   // (8,2,256,64)
  const float* w_down  = (const float*)d_in[4];   // (65536,512)
  const float* w_up    = (const float*)d_in[5];   // (65536,512)
  float* out = (float*)d_out;                     // (2,512,512)

  zero_kernel<<<1024, 256>>>(out);
  gemm_qh_kernel<<<dim3(8, 8), 256>>>(queries, Wq, bq);
  scores_kernel<<<dim3(1024, 8), 256>>>(keys);
  topk_kernel<<<8192, 256>>>();
  gemm_s_kernel<<<dim3(8, 512), 256>>>(queries, w_down);
  gemm_out_kernel<<<dim3(4, 8, 32), 256>>>(w_up, out);
}

// round 4
// speedup vs baseline: 2.0341x; 2.0341x over previous
#include <cuda_runtime.h>
#include <cuda_bf16.h>
#include <cstdint>
#include <math.h>

#define NTOK 1024
#define DIM  512
#define NHEAD 8
#define EXP  256
#define NE   65536
#define KSEL 16

// ======================= device scratch ======================================
__device__ float g_qh[NTOK * NHEAD * 128];
__device__ float g_s1[NTOK * NHEAD * EXP];
__device__ float g_s2[NTOK * NHEAD * EXP];
__device__ float g_P[NE];
__device__ __align__(128) __nv_bfloat16 g_Q_hi[NTOK * DIM];
__device__ __align__(128) __nv_bfloat16 g_Q_lo[NTOK * DIM];
__device__ __align__(128) __nv_bfloat16 g_Wd_hi[(size_t)NE * DIM];
__device__ __align__(128) __nv_bfloat16 g_Wd_lo[(size_t)NE * DIM];
__device__ __align__(128) __nv_bfloat16 g_WuT_hi[(size_t)DIM * NE];
__device__ __align__(128) __nv_bfloat16 g_WuT_lo[(size_t)DIM * NE];
__device__ __align__(128) __nv_bfloat16 g_S_hi[(size_t)NTOK * NE];
__device__ __align__(128) __nv_bfloat16 g_S_lo[(size_t)NTOK * NE];

// ======================= small helpers =======================================
__device__ __forceinline__ void mma16816(float c[4], const uint32_t a[4],
                                         uint32_t b0, uint32_t b1) {
  asm volatile(
      "mma.sync.aligned.m16n8k16.row.col.f32.bf16.bf16.f32 "
      "{%0,%1,%2,%3}, {%4,%5,%6,%7}, {%8,%9}, {%0,%1,%2,%3};"
      : "+f"(c[0]), "+f"(c[1]), "+f"(c[2]), "+f"(c[3])
      : "r"(a[0]), "r"(a[1]), "r"(a[2]), "r"(a[3]), "r"(b0), "r"(b1));
}
__device__ __forceinline__ void ldsm4(uint32_t r[4], uint32_t addr) {
  asm volatile("ldmatrix.sync.aligned.m8n8.x4.shared.b16 {%0,%1,%2,%3}, [%4];"
               : "=r"(r[0]), "=r"(r[1]), "=r"(r[2]), "=r"(r[3]) : "r"(addr));
}
__device__ __forceinline__ void cp16(uint32_t dst, const void* src) {
  asm volatile("cp.async.cg.shared.global [%0], [%1], 16;" :: "r"(dst), "l"(src));
}
#define CP_COMMIT asm volatile("cp.async.commit_group;" ::: "memory")
#define CP_WAIT1  asm volatile("cp.async.wait_group 1;" ::: "memory")
#define CP_WAIT0  asm volatile("cp.async.wait_group 0;" ::: "memory")

// split one fp32 into (hi, lo) bf16 pair packed as bf16x2 words
__device__ __forceinline__ void split2(float x0, float x1, uint32_t& hw, uint32_t& lw) {
  __nv_bfloat16 h0 = __float2bfloat16(x0);
  __nv_bfloat16 h1 = __float2bfloat16(x1);
  __nv_bfloat16 l0 = __float2bfloat16(x0 - __bfloat162float(h0));
  __nv_bfloat16 l1 = __float2bfloat16(x1 - __bfloat162float(h1));
  hw = (uint32_t)__bfloat16_as_ushort(h0) | ((uint32_t)__bfloat16_as_ushort(h1) << 16);
  lw = (uint32_t)__bfloat16_as_ushort(l0) | ((uint32_t)__bfloat16_as_ushort(l1) << 16);
}

// ======================= zero ================================================
__global__ void zero_kernel(float* __restrict__ out) {
  int i = blockIdx.x * blockDim.x + threadIdx.x;
  int stride = gridDim.x * blockDim.x;
  for (int j = i; j < NE; j += stride) g_P[j] = 0.f;
  for (int j = i; j < NTOK * DIM; j += stride) out[j] = 0.f;
}

// ======================= fp32 -> (hi, lo) bf16 split (globals written from
// DEVICE code — never pass __device__ globals as kernel args from host!) ====
__device__ __forceinline__ void split_body(const float* __restrict__ src,
                                           __nv_bfloat16* hi, __nv_bfloat16* lo,
                                           int i) {
  const float4* s = (const float4*)src + (size_t)i * 2;
  float4 a = s[0], b = s[1];
  float xs[8] = {a.x, a.y, a.z, a.w, b.x, b.y, b.z, b.w};
  uint32_t hw[4], lw[4];
#pragma unroll
  for (int r = 0; r < 4; r++) split2(xs[2 * r], xs[2 * r + 1], hw[r], lw[r]);
  ((uint4*)hi)[i] = make_uint4(hw[0], hw[1], hw[2], hw[3]);
  ((uint4*)lo)[i] = make_uint4(lw[0], lw[1], lw[2], lw[3]);
}
__global__ void split_q_kernel(const float* __restrict__ src) {
  int i = blockIdx.x * blockDim.x + threadIdx.x;
  if (i < NTOK * DIM / 8) split_body(src, g_Q_hi, g_Q_lo, i);
}
__global__ void split_wd_kernel(const float* __restrict__ src) {
  int i = blockIdx.x * blockDim.x + threadIdx.x;
  if (i < (int)((size_t)NE * DIM / 8)) split_body(src, g_Wd_hi, g_Wd_lo, i);
}

// Wu [65536 x 512] fp32 -> WuT_hi/lo [512 x 65536] bf16 (transposed split)
__global__ void trans_split_kernel(const float* __restrict__ W) {
  __shared__ float t[32][33];
  int k0 = blockIdx.x * 32, n0 = blockIdx.y * 32;
  int tx = threadIdx.x, ty = threadIdx.y;
#pragma unroll
  for (int i = 0; i < 4; i++)
    t[ty + 8 * i][tx] = W[(size_t)(k0 + ty + 8 * i) * 512 + n0 + tx];
  __syncthreads();
#pragma unroll
  for (int i = 0; i < 4; i++) {
    float v = t[tx][ty + 8 * i];
    __nv_bfloat16 h = __float2bfloat16(v);
    __nv_bfloat16 l = __float2bfloat16(v - __bfloat162float(h));
    size_t o = (size_t)(n0 + ty + 8 * i) * NE + k0 + tx;
    g_WuT_hi[o] = h;
    g_WuT_lo[o] = l;
  }
}

// ======================= qh = Q @ Wq^T + bq (SIMT fp32) ======================
__global__ __launch_bounds__(256) void gemm_qh_kernel(
    const float* __restrict__ A, const float* __restrict__ B,
    const float* __restrict__ bias) {
  __shared__ float As[16][128];
  __shared__ float Bs[16][128];
  int m0 = blockIdx.x * 128, n0 = blockIdx.y * 128;
  int tid = threadIdx.x;
  int tx = tid & 15, ty = tid >> 4;
  int lr = tid >> 2, lc = tid & 3;
  float acc[8][8];
#pragma unroll
  for (int i = 0; i < 8; i++)
#pragma unroll
    for (int j = 0; j < 8; j++) acc[i][j] = 0.f;
  for (int k0 = 0; k0 < 512; k0 += 16) {
#pragma unroll
    for (int half = 0; half < 2; half++) {
      int r = lr + half * 64;
      float4 va = *(const float4*)&A[(size_t)(m0 + r) * 512 + k0 + lc * 4];
      As[lc * 4 + 0][r] = va.x; As[lc * 4 + 1][r] = va.y;
      As[lc * 4 + 2][r] = va.z; As[lc * 4 + 3][r] = va.w;
      float4 vb = *(const float4*)&B[(size_t)(n0 + r) * 512 + k0 + lc * 4];
      Bs[lc * 4 + 0][r] = vb.x; Bs[lc * 4 + 1][r] = vb.y;
      Bs[lc * 4 + 2][r] = vb.z; Bs[lc * 4 + 3][r] = vb.w;
    }
    __syncthreads();
#pragma unroll
    for (int k = 0; k < 16; k++) {
      float a[8], b[8];
      *(float4*)&a[0] = *(const float4*)&As[k][ty * 8];
      *(float4*)&a[4] = *(const float4*)&As[k][ty * 8 + 4];
      *(float4*)&b[0] = *(const float4*)&Bs[k][tx * 8];
      *(float4*)&b[4] = *(const float4*)&Bs[k][tx * 8 + 4];
#pragma unroll
      for (int i = 0; i < 8; i++)
#pragma unroll
        for (int j = 0; j < 8; j++) acc[i][j] += a[i] * b[j];
    }
    __syncthreads();
  }
#pragma unroll
  for (int i = 0; i < 8; i++) {
    int m = m0 + ty * 8 + i;
#pragma unroll
    for (int j = 0; j < 8; j++) {
      int n = n0 + tx * 8 + j;
      g_qh[(size_t)m * 1024 + n] = acc[i][j] + bias[n];
    }
  }
}

// ======================= scores ==============================================
__global__ __launch_bounds__(256) void scores_kernel(const float* __restrict__ keys) {
  int nt = blockIdx.x, h = blockIdx.y;
  __shared__ float q[128];
  __shared__ float ks[64 * 65];
  int tid = threadIdx.x;
  if (tid < 128) q[tid] = g_qh[((size_t)nt * NHEAD + h) * 128 + tid];
  __syncthreads();
  for (int half = 0; half < 2; half++) {
    const float* qhp = q + half * 64;
    float* dst = (half == 0) ? g_s1 : g_s2;
    for (int et = 0; et < 4; et++) {
      const float* kp = keys + ((size_t)(h * 2 + half) * 256 + et * 64) * 64;
      for (int idx = tid; idx < 4096; idx += 256) {
        int r = idx >> 6, c = idx & 63;
        ks[r * 65 + c] = kp[idx];
      }
      __syncthreads();
      int el = tid >> 2, qq = tid & 3;
      float sum = 0.f;
#pragma unroll
      for (int c = 0; c < 16; c++)
        sum += qhp[qq * 16 + c] * ks[el * 65 + qq * 16 + c];
      sum += __shfl_xor_sync(0xffffffffu, sum, 1);
      sum += __shfl_xor_sync(0xffffffffu, sum, 2);
      if (qq == 0)
        dst[((size_t)nt * NHEAD + h) * EXP + et * 64 + el] = sum;
      __syncthreads();
    }
  }
}

// ======================= warp-level top-k ====================================
__device__ __forceinline__ void warp_top16(float v[8], int lid, float& mv, int& mi) {
  for (int k = 0; k < KSEL; k++) {
    float bv = v[0];
    int br = 0;
#pragma unroll
    for (int r = 1; r < 8; r++)
      if (v[r] > bv) { bv = v[r]; br = r; }
    int code = br * 32 + lid;
#pragma unroll
    for (int off = 16; off; off >>= 1) {
      float ov = __shfl_xor_sync(0xffffffffu, bv, off);
      int oc = __shfl_xor_sync(0xffffffffu, code, off);
      if (ov > bv || (ov == bv && oc < code)) { bv = ov; code = oc; }
    }
    if (lid == k) { mv = bv; mi = code; }
    int owner = code & 31, reg = code >> 5;
    if (lid == owner) {
#pragma unroll
      for (int r = 0; r < 8; r++)
        if (r == reg) v[r] = -INFINITY;
    }
  }
}

__global__ __launch_bounds__(256) void topk_kernel() {
  int lid = threadIdx.x & 31;
  int w = threadIdx.x >> 5;
  int row = blockIdx.x * 8 + w;
  float v[8];
  float m1v = 0.f, m2v = 0.f, m3v = 0.f;
  int m1i = 0, m2i = 0, m3i = 0;

  const float* s1 = g_s1 + (size_t)row * EXP;
#pragma unroll
  for (int r = 0; r < 8; r++) v[r] = s1[r * 32 + lid];
  warp_top16(v, lid, m1v, m1i);

  const float* s2 = g_s2 + (size_t)row * EXP;
#pragma unroll
  for (int r = 0; r < 8; r++) v[r] = s2[r * 32 + lid];
  warp_top16(v, lid, m2v, m2i);

#pragma unroll
  for (int r = 0; r < 8; r++) {
    int t = r * 32 + lid;
    float a = __shfl_sync(0xffffffffu, m1v, t >> 4);
    float b = __shfl_sync(0xffffffffu, m2v, t & 15);
    v[r] = a + b;
  }
  warp_top16(v, lid, m3v, m3i);

  float mx = __shfl_sync(0xffffffffu, m3v, 0);
  float p = (lid < 16) ? expf(m3v - mx) : 0.f;
  float sum = p;
#pragma unroll
  for (int off = 16; off; off >>= 1) sum += __shfl_xor_sync(0xffffffffu, sum, off);
  float inv = 1.0f / sum;
  int i1 = __shfl_sync(0xffffffffu, m1i, (m3i >> 4) & 15);
  int i2 = __shfl_sync(0xffffffffu, m2i, m3i & 15);
  if (lid < 16) atomicAdd(&g_P[i1 * EXP + i2], p * inv);
}

// ======================= HMMA mainloop =======================================
// CTA 128x128, 8 warps (2m x 4n), warp tile 64x32. K-chunk = 16 bf16 (32B rows).
// 3-stage cp.async ring in 48KB static smem; hi/lo split accumulated 3-term.
// Stage layout: Ah @ +0 (4KB), Al @ +4096, Bh @ +8192, Bl @ +12288.
__device__ __forceinline__ void mainloop(
    const char* Ahb, const char* Alb, const char* Bhb, const char* Blb,
    size_t sA, size_t sB, int NC, float acc[4][4][4], char* sm) {
  uint32_t smb = (uint32_t)__cvta_generic_to_shared(sm);
  int tid = threadIdx.x, lane = tid & 31, wid = tid >> 5;
  int wm = (wid & 1) * 64, wn = (wid >> 1) * 32;
  int arow = ((lane >> 3) & 1) * 8 + (lane & 7);
  int aseg = lane >> 4;

  int lr = tid >> 1, ls = tid & 1;
  uint32_t doff = lr * 32 + ((ls ^ ((lr >> 2) & 1)) << 4);
  const char* pA_h = Ahb + (size_t)lr * sA + ls * 16;
  const char* pA_l = Alb + (size_t)lr * sA + ls * 16;
  const char* pB_h = Bhb + (size_t)lr * sB + ls * 16;
  const char* pB_l = Blb + (size_t)lr * sB + ls * 16;

#define ISSUE(ck) do {                                    \
    uint32_t _b = smb + ((ck) % 3) * 16384;               \
    size_t _ko = (size_t)(ck) * 32;                       \
    cp16(_b + doff, pA_h + _ko);                          \
    cp16(_b + 4096 + doff, pA_l + _ko);                   \
    cp16(_b + 8192 + doff, pB_h + _ko);                   \
    cp16(_b + 12288 + doff, pB_l + _ko);                  \
    CP_COMMIT;                                            \
  } while (0)

  ISSUE(0);
  ISSUE(1);
  for (int ck = 0; ck < NC; ck++) {
    // ensure group ck has landed: with one group possibly still in flight use
    // wait_group 1, but on the FINAL chunk only group ck remains — drain all.
    if (ck == NC - 1) { CP_WAIT0; } else { CP_WAIT1; }
    __syncthreads();
    if (ck + 2 < NC) ISSUE(ck + 2);
    uint32_t b = smb + (ck % 3) * 16384;
    uint32_t A[4][4], Bh[2][4], Bl[2][4];
#pragma unroll
    for (int p = 0; p < 2; p++) {
      int row = wn + p * 16 + arow;
      uint32_t ad = b + 8192 + row * 32 + ((aseg ^ ((row >> 2) & 1)) << 4);
      ldsm4(Bh[p], ad);
      ldsm4(Bl[p], ad + 4096);
    }
#pragma unroll
    for (int mt = 0; mt < 4; mt++) {
      int row = wm + mt * 16 + arow;
      uint32_t ad = b + row * 32 + ((aseg ^ ((row >> 2) & 1)) << 4);
      ldsm4(A[mt], ad);
    }
#pragma unroll
    for (int mt = 0; mt < 4; mt++)
#pragma unroll
      for (int nt = 0; nt < 4; nt++) {
        int p = nt >> 1, j = nt & 1;
        mma16816(acc[mt][nt], A[mt], Bh[p][j], Bh[p][j + 2]);
        mma16816(acc[mt][nt], A[mt], Bl[p][j], Bl[p][j + 2]);
      }
#pragma unroll
    for (int mt = 0; mt < 4; mt++) {
      int row = wm + mt * 16 + arow;
      uint32_t ad = b + 4096 + row * 32 + ((aseg ^ ((row >> 2) & 1)) << 4);
      ldsm4(A[mt], ad);
    }
#pragma unroll
    for (int mt = 0; mt < 4; mt++)
#pragma unroll
      for (int nt = 0; nt < 4; nt++) {
        int p = nt >> 1, j = nt & 1;
        mma16816(acc[mt][nt], A[mt], Bh[p][j], Bh[p][j + 2]);
      }
  }
#undef ISSUE
}

// ---------- D1: S' = relu(Q @ Wd^T) * P ; M=1024, N=65536, K=512 -------------
__global__ __launch_bounds__(256) void d1_kernel() {
  __shared__ __align__(1024) char sm[49152];
  int m0 = blockIdx.x * 128, n0 = blockIdx.y * 128;
  float acc[4][4][4];
#pragma unroll
  for (int a = 0; a < 4; a++)
#pragma unroll
    for (int c = 0; c < 4; c++)
#pragma unroll
      for (int d = 0; d < 4; d++) acc[a][c][d] = 0.f;

  mainloop((const char*)(g_Q_hi + (size_t)m0 * 512),
           (const char*)(g_Q_lo + (size_t)m0 * 512),
           (const char*)(g_Wd_hi + (size_t)n0 * 512),
           (const char*)(g_Wd_lo + (size_t)n0 * 512),
           1024, 1024, 32, acc, sm);

  int tid = threadIdx.x, lane = tid & 31, wid = tid >> 5;
  int wm = (wid & 1) * 64, wn = (wid >> 1) * 32;
  int r0 = lane >> 2, cc = (lane & 3) * 2;
#pragma unroll
  for (int nt = 0; nt < 4; nt++) {
    int n = n0 + wn + nt * 8 + cc;
    float2 P2 = *(const float2*)&g_P[n];
#pragma unroll
    for (int mt = 0; mt < 4; mt++) {
#pragma unroll
      for (int h = 0; h < 2; h++) {
        int m = m0 + wm + mt * 16 + r0 + h * 8;
        float v0 = fmaxf(acc[mt][nt][2 * h + 0], 0.f) * P2.x;
        float v1 = fmaxf(acc[mt][nt][2 * h + 1], 0.f) * P2.y;
        uint32_t hw, lw;
        split2(v0, v1, hw, lw);
        size_t o = (size_t)m * NE + n;
        *(uint32_t*)&g_S_hi[o] = hw;
        *(uint32_t*)&g_S_lo[o] = lw;
      }
    }
  }
}

// ---------- D2: out += S' @ Wu ; M=1024, N=512, K=65536, split-K=16 ----------
__global__ __launch_bounds__(256) void d2_kernel(float* __restrict__ out) {
  __shared__ __align__(1024) char sm[49152];
  int n0 = blockIdx.x * 128, m0 = blockIdx.y * 128;
  size_t kb = (size_t)blockIdx.z * 4096;
  float acc[4][4][4];
#pragma unroll
  for (int a = 0; a < 4; a++)
#pragma unroll
    for (int c = 0; c < 4; c++)
#pragma unroll
      for (int d = 0; d < 4; d++) acc[a][c][d] = 0.f;

  mainloop((const char*)(g_S_hi + (size_t)m0 * NE + kb),
           (const char*)(g_S_lo + (size_t)m0 * NE + kb),
           (const char*)(g_WuT_hi + (size_t)n0 * NE + kb),
           (const char*)(g_WuT_lo + (size_t)n0 * NE + kb),
           131072, 131072, 256, acc, sm);

  int tid = threadIdx.x, lane = tid & 31, wid = tid >> 5;
  int wm = (wid & 1) * 64, wn = (wid >> 1) * 32;
  int r0 = lane >> 2, cc = (lane & 3) * 2;
#pragma unroll
  for (int nt = 0; nt < 4; nt++) {
    int n = n0 + wn + nt * 8 + cc;
#pragma unroll
    for (int mt = 0; mt < 4; mt++) {
#pragma unroll
      for (int h = 0; h < 2; h++) {
        int m = m0 + wm + mt * 16 + r0 + h * 8;
        atomicAdd(&out[(size_t)m * DIM + n], acc[mt][nt][2 * h + 0]);
        atomicAdd(&out[(size_t)m * DIM + n + 1], acc[mt][nt][2 * h + 1]);
      }
    }
  }
}

// ======================= launch ==============================================
extern "C" void kernel_launch(void* const* d_in, const int* in_sizes, int n_in,
                              void* d_out, int out_size) {
  const float* queries = (const float*)d_in[0];
  const float* Wq      = (const float*)d_in[1];
  const float* bq      = (const float*)d_in[2];
  const float* keys    = (const float*)d_in[3];
  const float* w_down  = (const float*)d_in[4];
  const float* w_up    = (const float*)d_in[5];
  float* out = (float*)d_out;

  zero_kernel<<<1024, 256>>>(out);
  split_q_kernel<<<256, 256>>>(queries);
  split_wd_kernel<<<16384, 256>>>(w_down);
  trans_split_kernel<<<dim3(2048, 16), dim3(32, 8)>>>(w_up);
  gemm_qh_kernel<<<dim3(8, 8), 256>>>(queries, Wq, bq);
  scores_kernel<<<dim3(1024, 8), 256>>>(keys);
  topk_kernel<<<1024, 256>>>();
  d1_kernel<<<dim3(8, 512), 256>>>();
  d2_kernel<<<dim3(4, 8, 16), 256>>>(out);
}

// round 5
// speedup vs baseline: 2.1236x; 1.0440x over previous
#include <cuda_runtime.h>
#include <cuda_bf16.h>
#include <cstdint>
#include <math.h>

#define NTOK 1024
#define DIM  512
#define NHEAD 8
#define EXP  256
#define NE   65536
#define KSEL 16

// ======================= device scratch ======================================
__device__ float g_qh[NTOK * NHEAD * 128];
__device__ float g_s1[NTOK * NHEAD * EXP];
__device__ float g_s2[NTOK * NHEAD * EXP];
__device__ float g_P[NE];
__device__ __align__(128) __nv_bfloat16 g_Q_hi[NTOK * DIM];
__device__ __align__(128) __nv_bfloat16 g_Q_lo[NTOK * DIM];
__device__ __align__(128) __nv_bfloat16 g_Wd_hi[(size_t)NE * DIM];
__device__ __align__(128) __nv_bfloat16 g_Wd_lo[(size_t)NE * DIM];
__device__ __align__(128) __nv_bfloat16 g_WuT_hi[(size_t)DIM * NE];
__device__ __align__(128) __nv_bfloat16 g_WuT_lo[(size_t)DIM * NE];
__device__ __align__(128) __nv_bfloat16 g_S_hi[(size_t)NTOK * NE];
__device__ __align__(128) __nv_bfloat16 g_S_lo[(size_t)NTOK * NE];

// ======================= small helpers =======================================
__device__ __forceinline__ void mma16816(float c[4], const uint32_t a[4],
                                         uint32_t b0, uint32_t b1) {
  asm volatile(
      "mma.sync.aligned.m16n8k16.row.col.f32.bf16.bf16.f32 "
      "{%0,%1,%2,%3}, {%4,%5,%6,%7}, {%8,%9}, {%0,%1,%2,%3};"
      : "+f"(c[0]), "+f"(c[1]), "+f"(c[2]), "+f"(c[3])
      : "r"(a[0]), "r"(a[1]), "r"(a[2]), "r"(a[3]), "r"(b0), "r"(b1));
}
__device__ __forceinline__ void ldsm4(uint32_t r[4], uint32_t addr) {
  asm volatile("ldmatrix.sync.aligned.m8n8.x4.shared.b16 {%0,%1,%2,%3}, [%4];"
               : "=r"(r[0]), "=r"(r[1]), "=r"(r[2]), "=r"(r[3]) : "r"(addr));
}
__device__ __forceinline__ void cp16(uint32_t dst, const void* src) {
  asm volatile("cp.async.cg.shared.global [%0], [%1], 16;" :: "r"(dst), "l"(src));
}
#define CP_COMMIT asm volatile("cp.async.commit_group;" ::: "memory")
#define CP_WAIT1  asm volatile("cp.async.wait_group 1;" ::: "memory")
#define CP_WAIT0  asm volatile("cp.async.wait_group 0;" ::: "memory")

__device__ __forceinline__ void split2(float x0, float x1, uint32_t& hw, uint32_t& lw) {
  __nv_bfloat16 h0 = __float2bfloat16(x0);
  __nv_bfloat16 h1 = __float2bfloat16(x1);
  __nv_bfloat16 l0 = __float2bfloat16(x0 - __bfloat162float(h0));
  __nv_bfloat16 l1 = __float2bfloat16(x1 - __bfloat162float(h1));
  hw = (uint32_t)__bfloat16_as_ushort(h0) | ((uint32_t)__bfloat16_as_ushort(h1) << 16);
  lw = (uint32_t)__bfloat16_as_ushort(l0) | ((uint32_t)__bfloat16_as_ushort(l1) << 16);
}

// ======================= zero ================================================
__global__ void zero_kernel(float* __restrict__ out) {
  int i = blockIdx.x * blockDim.x + threadIdx.x;
  int stride = gridDim.x * blockDim.x;
  for (int j = i; j < NE; j += stride) g_P[j] = 0.f;
  for (int j = i; j < NTOK * DIM; j += stride) out[j] = 0.f;
}

// ======================= fp32 -> (hi, lo) split ==============================
__device__ __forceinline__ void split_body(const float* __restrict__ src,
                                           __nv_bfloat16* hi, __nv_bfloat16* lo,
                                           int i) {
  const float4* s = (const float4*)src + (size_t)i * 2;
  float4 a = s[0], b = s[1];
  float xs[8] = {a.x, a.y, a.z, a.w, b.x, b.y, b.z, b.w};
  uint32_t hw[4], lw[4];
#pragma unroll
  for (int r = 0; r < 4; r++) split2(xs[2 * r], xs[2 * r + 1], hw[r], lw[r]);
  ((uint4*)hi)[i] = make_uint4(hw[0], hw[1], hw[2], hw[3]);
  ((uint4*)lo)[i] = make_uint4(lw[0], lw[1], lw[2], lw[3]);
}
__global__ void split_q_kernel(const float* __restrict__ src) {
  int i = blockIdx.x * blockDim.x + threadIdx.x;
  if (i < NTOK * DIM / 8) split_body(src, g_Q_hi, g_Q_lo, i);
}
__global__ void split_wd_kernel(const float* __restrict__ src) {
  int i = blockIdx.x * blockDim.x + threadIdx.x;
  if (i < (int)((size_t)NE * DIM / 8)) split_body(src, g_Wd_hi, g_Wd_lo, i);
}

// Wu [65536 x 512] fp32 -> WuT_hi/lo [512 x 65536] bf16 (transposed split)
__global__ void trans_split_kernel(const float* __restrict__ W) {
  __shared__ float t[32][33];
  int k0 = blockIdx.x * 32, n0 = blockIdx.y * 32;
  int tx = threadIdx.x, ty = threadIdx.y;
#pragma unroll
  for (int i = 0; i < 4; i++)
    t[ty + 8 * i][tx] = W[(size_t)(k0 + ty + 8 * i) * 512 + n0 + tx];
  __syncthreads();
#pragma unroll
  for (int i = 0; i < 4; i++) {
    float v = t[tx][ty + 8 * i];
    __nv_bfloat16 h = __float2bfloat16(v);
    __nv_bfloat16 l = __float2bfloat16(v - __bfloat162float(h));
    size_t o = (size_t)(n0 + ty + 8 * i) * NE + k0 + tx;
    g_WuT_hi[o] = h;
    g_WuT_lo[o] = l;
  }
}

// ======================= qh = Q @ Wq^T + bq (SIMT fp32) ======================
__global__ __launch_bounds__(256) void gemm_qh_kernel(
    const float* __restrict__ A, const float* __restrict__ B,
    const float* __restrict__ bias) {
  __shared__ float As[16][128];
  __shared__ float Bs[16][128];
  int m0 = blockIdx.x * 128, n0 = blockIdx.y * 128;
  int tid = threadIdx.x;
  int tx = tid & 15, ty = tid >> 4;
  int lr = tid >> 2, lc = tid & 3;
  float acc[8][8];
#pragma unroll
  for (int i = 0; i < 8; i++)
#pragma unroll
    for (int j = 0; j < 8; j++) acc[i][j] = 0.f;
  for (int k0 = 0; k0 < 512; k0 += 16) {
#pragma unroll
    for (int half = 0; half < 2; half++) {
      int r = lr + half * 64;
      float4 va = *(const float4*)&A[(size_t)(m0 + r) * 512 + k0 + lc * 4];
      As[lc * 4 + 0][r] = va.x; As[lc * 4 + 1][r] = va.y;
      As[lc * 4 + 2][r] = va.z; As[lc * 4 + 3][r] = va.w;
      float4 vb = *(const float4*)&B[(size_t)(n0 + r) * 512 + k0 + lc * 4];
      Bs[lc * 4 + 0][r] = vb.x; Bs[lc * 4 + 1][r] = vb.y;
      Bs[lc * 4 + 2][r] = vb.z; Bs[lc * 4 + 3][r] = vb.w;
    }
    __syncthreads();
#pragma unroll
    for (int k = 0; k < 16; k++) {
      float a[8], b[8];
      *(float4*)&a[0] = *(const float4*)&As[k][ty * 8];
      *(float4*)&a[4] = *(const float4*)&As[k][ty * 8 + 4];
      *(float4*)&b[0] = *(const float4*)&Bs[k][tx * 8];
      *(float4*)&b[4] = *(const float4*)&Bs[k][tx * 8 + 4];
#pragma unroll
      for (int i = 0; i < 8; i++)
#pragma unroll
        for (int j = 0; j < 8; j++) acc[i][j] += a[i] * b[j];
    }
    __syncthreads();
  }
#pragma unroll
  for (int i = 0; i < 8; i++) {
    int m = m0 + ty * 8 + i;
#pragma unroll
    for (int j = 0; j < 8; j++) {
      int n = n0 + tx * 8 + j;
      g_qh[(size_t)m * 1024 + n] = acc[i][j] + bias[n];
    }
  }
}

// ======================= scores ==============================================
__global__ __launch_bounds__(256) void scores_kernel(const float* __restrict__ keys) {
  int nt = blockIdx.x, h = blockIdx.y;
  __shared__ float q[128];
  __shared__ float ks[64 * 65];
  int tid = threadIdx.x;
  if (tid < 128) q[tid] = g_qh[((size_t)nt * NHEAD + h) * 128 + tid];
  __syncthreads();
  for (int half = 0; half < 2; half++) {
    const float* qhp = q + half * 64;
    float* dst = (half == 0) ? g_s1 : g_s2;
    for (int et = 0; et < 4; et++) {
      const float* kp = keys + ((size_t)(h * 2 + half) * 256 + et * 64) * 64;
      for (int idx = tid; idx < 4096; idx += 256) {
        int r = idx >> 6, c = idx & 63;
        ks[r * 65 + c] = kp[idx];
      }
      __syncthreads();
      int el = tid >> 2, qq = tid & 3;
      float sum = 0.f;
#pragma unroll
      for (int c = 0; c < 16; c++)
        sum += qhp[qq * 16 + c] * ks[el * 65 + qq * 16 + c];
      sum += __shfl_xor_sync(0xffffffffu, sum, 1);
      sum += __shfl_xor_sync(0xffffffffu, sum, 2);
      if (qq == 0)
        dst[((size_t)nt * NHEAD + h) * EXP + et * 64 + el] = sum;
      __syncthreads();
    }
  }
}

// ======================= warp-level top-k ====================================
__device__ __forceinline__ void warp_top16(float v[8], int lid, float& mv, int& mi) {
  for (int k = 0; k < KSEL; k++) {
    float bv = v[0];
    int br = 0;
#pragma unroll
    for (int r = 1; r < 8; r++)
      if (v[r] > bv) { bv = v[r]; br = r; }
    int code = br * 32 + lid;
#pragma unroll
    for (int off = 16; off; off >>= 1) {
      float ov = __shfl_xor_sync(0xffffffffu, bv, off);
      int oc = __shfl_xor_sync(0xffffffffu, code, off);
      if (ov > bv || (ov == bv && oc < code)) { bv = ov; code = oc; }
    }
    if (lid == k) { mv = bv; mi = code; }
    int owner = code & 31, reg = code >> 5;
    if (lid == owner) {
#pragma unroll
      for (int r = 0; r < 8; r++)
        if (r == reg) v[r] = -INFINITY;
    }
  }
}

__global__ __launch_bounds__(256) void topk_kernel() {
  int lid = threadIdx.x & 31;
  int w = threadIdx.x >> 5;
  int row = blockIdx.x * 8 + w;
  float v[8];
  float m1v = 0.f, m2v = 0.f, m3v = 0.f;
  int m1i = 0, m2i = 0, m3i = 0;

  const float* s1 = g_s1 + (size_t)row * EXP;
#pragma unroll
  for (int r = 0; r < 8; r++) v[r] = s1[r * 32 + lid];
  warp_top16(v, lid, m1v, m1i);

  const float* s2 = g_s2 + (size_t)row * EXP;
#pragma unroll
  for (int r = 0; r < 8; r++) v[r] = s2[r * 32 + lid];
  warp_top16(v, lid, m2v, m2i);

#pragma unroll
  for (int r = 0; r < 8; r++) {
    int t = r * 32 + lid;
    float a = __shfl_sync(0xffffffffu, m1v, t >> 4);
    float b = __shfl_sync(0xffffffffu, m2v, t & 15);
    v[r] = a + b;
  }
  warp_top16(v, lid, m3v, m3i);

  float mx = __shfl_sync(0xffffffffu, m3v, 0);
  float p = (lid < 16) ? expf(m3v - mx) : 0.f;
  float sum = p;
#pragma unroll
  for (int off = 16; off; off >>= 1) sum += __shfl_xor_sync(0xffffffffu, sum, off);
  float inv = 1.0f / sum;
  int i1 = __shfl_sync(0xffffffffu, m1i, (m3i >> 4) & 15);
  int i2 = __shfl_sync(0xffffffffu, m2i, m3i & 15);
  if (lid < 16) atomicAdd(&g_P[i1 * EXP + i2], p * inv);
}

// ======================= HMMA mainloop v2 =====================================
// CTA 128(M) x 256(N), 8 warps (2m x 4n), warp tile 64x64. K-chunk = 32 (64B).
// 3-stage cp.async ring in 144KB dynamic smem. hi/lo 3-term accumulation.
// 64B-row swizzle: seg' = seg ^ ((row>>1)&3) -> conflict-free ldsm + STS.
#define BM 128
#define BN 256
#define SM_AH 0
#define SM_AL 8192
#define SM_BH 16384
#define SM_BL 32768
#define STAGE_BYTES 49152
#define DSMEM_SZ (3 * STAGE_BYTES)

__device__ __forceinline__ uint32_t swz(int row, int seg) {
  return (uint32_t)(row * 64 + ((seg ^ ((row >> 1) & 3)) << 4));
}

__device__ __forceinline__ void issue_chunk(
    uint32_t smb, int stage, const char* Ah, const char* Al,
    const char* Bh, const char* Bl, size_t sA, size_t sB, int ck, int tid) {
  uint32_t base = smb + stage * STAGE_BYTES;
  size_t ko = (size_t)ck * 64;
#pragma unroll
  for (int t = 0; t < 2; t++) {
    int q = tid + t * 256;
    int row = q >> 2, seg = q & 3;
    uint32_t d = base + swz(row, seg);
    size_t so = (size_t)row * sA + ko + seg * 16;
    cp16(d + SM_AH, Ah + so);
    cp16(d + SM_AL, Al + so);
  }
#pragma unroll
  for (int t = 0; t < 4; t++) {
    int q = tid + t * 256;
    int row = q >> 2, seg = q & 3;
    uint32_t d = base + swz(row, seg);
    size_t so = (size_t)row * sB + ko + seg * 16;
    cp16(d + SM_BH, Bh + so);
    cp16(d + SM_BL, Bl + so);
  }
  CP_COMMIT;
}

__device__ __forceinline__ void mainloop2(
    const char* Ah, const char* Al, const char* Bh, const char* Bl,
    size_t sA, size_t sB, int NC, float acc[4][8][4], char* sm) {
  uint32_t smb = (uint32_t)__cvta_generic_to_shared(sm);
  int tid = threadIdx.x, lane = tid & 31, wid = tid >> 5;
  int wm = (wid & 1) * 64, wn = (wid >> 1) * 64;
  int arow = ((lane >> 3) & 1) * 8 + (lane & 7);
  int aseg = lane >> 4;  // 0 or 1 (k-half within a k16 step)

  issue_chunk(smb, 0, Ah, Al, Bh, Bl, sA, sB, 0, tid);
  issue_chunk(smb, 1, Ah, Al, Bh, Bl, sA, sB, 1, tid);

  for (int ck = 0; ck < NC; ck++) {
    if (ck == NC - 1) { CP_WAIT0; } else { CP_WAIT1; }
    __syncthreads();
    if (ck + 2 < NC)
      issue_chunk(smb, (ck + 2) % 3, Ah, Al, Bh, Bl, sA, sB, ck + 2, tid);
    uint32_t base = smb + (ck % 3) * STAGE_BYTES;
#pragma unroll
    for (int ks = 0; ks < 2; ks++) {
      int s = ks * 2 + aseg;
      uint32_t Af[4][4], Bf[4][4];
      // B hi fragments (n64 x k16)
#pragma unroll
      for (int g = 0; g < 4; g++) {
        int row = wn + g * 16 + arow;
        ldsm4(Bf[g], base + SM_BH + swz(row, s));
      }
      // A hi fragments (m64 x k16)
#pragma unroll
      for (int mt = 0; mt < 4; mt++) {
        int row = wm + mt * 16 + arow;
        ldsm4(Af[mt], base + SM_AH + swz(row, s));
      }
      // Ah * Bh
#pragma unroll
      for (int mt = 0; mt < 4; mt++)
#pragma unroll
        for (int nt = 0; nt < 8; nt++) {
          int g = nt >> 1, j = nt & 1;
          mma16816(acc[mt][nt], Af[mt], Bf[g][j], Bf[g][j + 2]);
        }
      // A lo fragments
      uint32_t Alf[4][4];
#pragma unroll
      for (int mt = 0; mt < 4; mt++) {
        int row = wm + mt * 16 + arow;
        ldsm4(Alf[mt], base + SM_AL + swz(row, s));
      }
      // Al * Bh
#pragma unroll
      for (int mt = 0; mt < 4; mt++)
#pragma unroll
        for (int nt = 0; nt < 8; nt++) {
          int g = nt >> 1, j = nt & 1;
          mma16816(acc[mt][nt], Alf[mt], Bf[g][j], Bf[g][j + 2]);
        }
      // B lo fragments (reuse Bf)
#pragma unroll
      for (int g = 0; g < 4; g++) {
        int row = wn + g * 16 + arow;
        ldsm4(Bf[g], base + SM_BL + swz(row, s));
      }
      // Ah * Bl
#pragma unroll
      for (int mt = 0; mt < 4; mt++)
#pragma unroll
        for (int nt = 0; nt < 8; nt++) {
          int g = nt >> 1, j = nt & 1;
          mma16816(acc[mt][nt], Af[mt], Bf[g][j], Bf[g][j + 2]);
        }
    }
  }
}

// ---------- D1: S' = relu(Q @ Wd^T) * P ; M=1024, N=65536, K=512 -------------
__global__ __launch_bounds__(256, 1) void d1_kernel() {
  extern __shared__ __align__(1024) char dynsm[];
  int m0 = blockIdx.x * BM, n0 = blockIdx.y * BN;
  float acc[4][8][4];
#pragma unroll
  for (int a = 0; a < 4; a++)
#pragma unroll
    for (int c = 0; c < 8; c++)
#pragma unroll
      for (int d = 0; d < 4; d++) acc[a][c][d] = 0.f;

  mainloop2((const char*)(g_Q_hi + (size_t)m0 * 512),
            (const char*)(g_Q_lo + (size_t)m0 * 512),
            (const char*)(g_Wd_hi + (size_t)n0 * 512),
            (const char*)(g_Wd_lo + (size_t)n0 * 512),
            1024, 1024, 16, acc, dynsm);

  int lane = threadIdx.x & 31, wid = threadIdx.x >> 5;
  int wm = (wid & 1) * 64, wn = (wid >> 1) * 64;
  int r0 = lane >> 2, cc = (lane & 3) * 2;
#pragma unroll
  for (int nt = 0; nt < 8; nt++) {
    int n = n0 + wn + nt * 8 + cc;
    float2 P2 = *(const float2*)&g_P[n];
#pragma unroll
    for (int mt = 0; mt < 4; mt++) {
#pragma unroll
      for (int h = 0; h < 2; h++) {
        int m = m0 + wm + mt * 16 + r0 + h * 8;
        float v0 = fmaxf(acc[mt][nt][2 * h + 0], 0.f) * P2.x;
        float v1 = fmaxf(acc[mt][nt][2 * h + 1], 0.f) * P2.y;
        uint32_t hw, lw;
        split2(v0, v1, hw, lw);
        size_t o = (size_t)m * NE + n;
        *(uint32_t*)&g_S_hi[o] = hw;
        *(uint32_t*)&g_S_lo[o] = lw;
      }
    }
  }
}

// ---------- D2: out += S' @ Wu ; M=1024, N=512, K=65536, split-K=32 ----------
__global__ __launch_bounds__(256, 1) void d2_kernel(float* __restrict__ out) {
  extern __shared__ __align__(1024) char dynsm[];
  int m0 = blockIdx.x * BM;          // x fastest: 8 m-tiles share kb slice in L2
  int n0 = blockIdx.y * BN;          // 2 n-tiles
  size_t kb = (size_t)blockIdx.z * 4096;  // byte offset (2048 k-elems per split)
  float acc[4][8][4];
#pragma unroll
  for (int a = 0; a < 4; a++)
#pragma unroll
    for (int c = 0; c < 8; c++)
#pragma unroll
      for (int d = 0; d < 4; d++) acc[a][c][d] = 0.f;

  mainloop2((const char*)g_S_hi + (size_t)m0 * 131072 + kb,
            (const char*)g_S_lo + (size_t)m0 * 131072 + kb,
            (const char*)g_WuT_hi + (size_t)n0 * 131072 + kb,
            (const char*)g_WuT_lo + (size_t)n0 * 131072 + kb,
            131072, 131072, 64, acc, dynsm);

  int lane = threadIdx.x & 31, wid = threadIdx.x >> 5;
  int wm = (wid & 1) * 64, wn = (wid >> 1) * 64;
  int r0 = lane >> 2, cc = (lane & 3) * 2;
#pragma unroll
  for (int nt = 0; nt < 8; nt++) {
    int n = n0 + wn + nt * 8 + cc;
#pragma unroll
    for (int mt = 0; mt < 4; mt++) {
#pragma unroll
      for (int h = 0; h < 2; h++) {
        int m = m0 + wm + mt * 16 + r0 + h * 8;
        atomicAdd(&out[(size_t)m * DIM + n], acc[mt][nt][2 * h + 0]);
        atomicAdd(&out[(size_t)m * DIM + n + 1], acc[mt][nt][2 * h + 1]);
      }
    }
  }
}

// ======================= launch ==============================================
extern "C" void kernel_launch(void* const* d_in, const int* in_sizes, int n_in,
                              void* d_out, int out_size) {
  const float* queries = (const float*)d_in[0];
  const float* Wq      = (const float*)d_in[1];
  const float* bq      = (const float*)d_in[2];
  const float* keys    = (const float*)d_in[3];
  const float* w_down  = (const float*)d_in[4];
  const float* w_up    = (const float*)d_in[5];
  float* out = (float*)d_out;

  cudaFuncSetAttribute(d1_kernel, cudaFuncAttributeMaxDynamicSharedMemorySize, DSMEM_SZ);
  cudaFuncSetAttribute(d2_kernel, cudaFuncAttributeMaxDynamicSharedMemorySize, DSMEM_SZ);

  zero_kernel<<<1024, 256>>>(out);
  split_q_kernel<<<256, 256>>>(queries);
  split_wd_kernel<<<16384, 256>>>(w_down);
  trans_split_kernel<<<dim3(2048, 16), dim3(32, 8)>>>(w_up);
  gemm_qh_kernel<<<dim3(8, 8), 256>>>(queries, Wq, bq);
  scores_kernel<<<dim3(1024, 8), 256>>>(keys);
  topk_kernel<<<1024, 256>>>();
  d1_kernel<<<dim3(8, 256), 256, DSMEM_SZ>>>();
  d2_kernel<<<dim3(8, 2, 32), 256, DSMEM_SZ>>>(out);
}

// round 6
// speedup vs baseline: 2.8206x; 1.3283x over previous
#include <cuda_runtime.h>
#include <cuda_fp16.h>
#include <cstdint>
#include <math.h>

#define NTOK 1024
#define DIM  512
#define NHEAD 8
#define EXP  256
#define NE   65536
#define KSEL 16

// ======================= device scratch ======================================
__device__ float g_qh[NTOK * NHEAD * 128];
__device__ float g_s1[NTOK * NHEAD * EXP];
__device__ float g_s2[NTOK * NHEAD * EXP];
__device__ float g_P[NE];
__device__ __align__(128) __half g_Qh[NTOK * DIM];
__device__ __align__(128) __half g_Ql[NTOK * DIM];
__device__ __align__(128) __half g_Wdh[(size_t)NE * DIM];    // 64 MB single fp16
__device__ __align__(128) __half g_WuTh[(size_t)DIM * NE];   // 64 MB single fp16
__device__ __align__(128) __half g_Sh[(size_t)NTOK * NE];    // 128 MB
__device__ __align__(128) __half g_Sl[(size_t)NTOK * NE];    // 128 MB

// ======================= small helpers =======================================
__device__ __forceinline__ void mma16816(float c[4], const uint32_t a[4],
                                         uint32_t b0, uint32_t b1) {
  asm volatile(
      "mma.sync.aligned.m16n8k16.row.col.f32.f16.f16.f32 "
      "{%0,%1,%2,%3}, {%4,%5,%6,%7}, {%8,%9}, {%0,%1,%2,%3};"
      : "+f"(c[0]), "+f"(c[1]), "+f"(c[2]), "+f"(c[3])
      : "r"(a[0]), "r"(a[1]), "r"(a[2]), "r"(a[3]), "r"(b0), "r"(b1));
}
__device__ __forceinline__ void ldsm4(uint32_t r[4], uint32_t addr) {
  asm volatile("ldmatrix.sync.aligned.m8n8.x4.shared.b16 {%0,%1,%2,%3}, [%4];"
               : "=r"(r[0]), "=r"(r[1]), "=r"(r[2]), "=r"(r[3]) : "r"(addr));
}
__device__ __forceinline__ void cp16(uint32_t dst, const void* src) {
  asm volatile("cp.async.cg.shared.global [%0], [%1], 16;" :: "r"(dst), "l"(src));
}
#define CP_COMMIT asm volatile("cp.async.commit_group;" ::: "memory")
#define CP_WAIT2  asm volatile("cp.async.wait_group 2;" ::: "memory")
#define CP_WAIT1  asm volatile("cp.async.wait_group 1;" ::: "memory")
#define CP_WAIT0  asm volatile("cp.async.wait_group 0;" ::: "memory")

// split one fp32 pair into (hi, lo) fp16 pairs packed as half2 words
__device__ __forceinline__ void split2h(float x0, float x1, uint32_t& hw, uint32_t& lw) {
  __half h0 = __float2half(x0);
  __half h1 = __float2half(x1);
  __half l0 = __float2half(x0 - __half2float(h0));
  __half l1 = __float2half(x1 - __half2float(h1));
  hw = (uint32_t)__half_as_ushort(h0) | ((uint32_t)__half_as_ushort(h1) << 16);
  lw = (uint32_t)__half_as_ushort(l0) | ((uint32_t)__half_as_ushort(l1) << 16);
}

// ======================= zero ================================================
__global__ void zero_kernel(float* __restrict__ out) {
  int i = blockIdx.x * blockDim.x + threadIdx.x;
  int stride = gridDim.x * blockDim.x;
  for (int j = i; j < NE; j += stride) g_P[j] = 0.f;
  for (int j = i; j < NTOK * DIM; j += stride) out[j] = 0.f;
}

// ======================= prep kernels ========================================
// Q fp32 -> Qh + Ql fp16 (hi/lo split)
__global__ void split_q_kernel(const float* __restrict__ src) {
  int i = blockIdx.x * blockDim.x + threadIdx.x;
  if (i >= NTOK * DIM / 8) return;
  const float4* s = (const float4*)src + (size_t)i * 2;
  float4 a = s[0], b = s[1];
  float xs[8] = {a.x, a.y, a.z, a.w, b.x, b.y, b.z, b.w};
  uint32_t hw[4], lw[4];
#pragma unroll
  for (int r = 0; r < 4; r++) split2h(xs[2 * r], xs[2 * r + 1], hw[r], lw[r]);
  ((uint4*)g_Qh)[i] = make_uint4(hw[0], hw[1], hw[2], hw[3]);
  ((uint4*)g_Ql)[i] = make_uint4(lw[0], lw[1], lw[2], lw[3]);
}

// Wd fp32 -> Wdh fp16 (single)
__global__ void conv_wd_kernel(const float* __restrict__ src) {
  int i = blockIdx.x * blockDim.x + threadIdx.x;
  if (i >= (int)((size_t)NE * DIM / 8)) return;
  const float4* s = (const float4*)src + (size_t)i * 2;
  float4 a = s[0], b = s[1];
  uint32_t w[4];
  w[0] = (uint32_t)__half_as_ushort(__float2half(a.x)) |
         ((uint32_t)__half_as_ushort(__float2half(a.y)) << 16);
  w[1] = (uint32_t)__half_as_ushort(__float2half(a.z)) |
         ((uint32_t)__half_as_ushort(__float2half(a.w)) << 16);
  w[2] = (uint32_t)__half_as_ushort(__float2half(b.x)) |
         ((uint32_t)__half_as_ushort(__float2half(b.y)) << 16);
  w[3] = (uint32_t)__half_as_ushort(__float2half(b.z)) |
         ((uint32_t)__half_as_ushort(__float2half(b.w)) << 16);
  ((uint4*)g_Wdh)[i] = make_uint4(w[0], w[1], w[2], w[3]);
}

// Wu [65536 x 512] fp32 -> WuT fp16 [512 x 65536] (transposed, single)
__global__ void trans_wu_kernel(const float* __restrict__ W) {
  __shared__ float t[32][33];
  int k0 = blockIdx.x * 32, n0 = blockIdx.y * 32;
  int tx = threadIdx.x, ty = threadIdx.y;
#pragma unroll
  for (int i = 0; i < 4; i++)
    t[ty + 8 * i][tx] = W[(size_t)(k0 + ty + 8 * i) * 512 + n0 + tx];
  __syncthreads();
#pragma unroll
  for (int i = 0; i < 4; i++) {
    float v = t[tx][ty + 8 * i];
    g_WuTh[(size_t)(n0 + ty + 8 * i) * NE + k0 + tx] = __float2half(v);
  }
}

// ======================= qh = Q @ Wq^T + bq (SIMT fp32) ======================
__global__ __launch_bounds__(256) void gemm_qh_kernel(
    const float* __restrict__ A, const float* __restrict__ B,
    const float* __restrict__ bias) {
  __shared__ float As[16][128];
  __shared__ float Bs[16][128];
  int m0 = blockIdx.x * 128, n0 = blockIdx.y * 128;
  int tid = threadIdx.x;
  int tx = tid & 15, ty = tid >> 4;
  int lr = tid >> 2, lc = tid & 3;
  float acc[8][8];
#pragma unroll
  for (int i = 0; i < 8; i++)
#pragma unroll
    for (int j = 0; j < 8; j++) acc[i][j] = 0.f;
  for (int k0 = 0; k0 < 512; k0 += 16) {
#pragma unroll
    for (int half = 0; half < 2; half++) {
      int r = lr + half * 64;
      float4 va = *(const float4*)&A[(size_t)(m0 + r) * 512 + k0 + lc * 4];
      As[lc * 4 + 0][r] = va.x; As[lc * 4 + 1][r] = va.y;
      As[lc * 4 + 2][r] = va.z; As[lc * 4 + 3][r] = va.w;
      float4 vb = *(const float4*)&B[(size_t)(n0 + r) * 512 + k0 + lc * 4];
      Bs[lc * 4 + 0][r] = vb.x; Bs[lc * 4 + 1][r] = vb.y;
      Bs[lc * 4 + 2][r] = vb.z; Bs[lc * 4 + 3][r] = vb.w;
    }
    __syncthreads();
#pragma unroll
    for (int k = 0; k < 16; k++) {
      float a[8], b[8];
      *(float4*)&a[0] = *(const float4*)&As[k][ty * 8];
      *(float4*)&a[4] = *(const float4*)&As[k][ty * 8 + 4];
      *(float4*)&b[0] = *(const float4*)&Bs[k][tx * 8];
      *(float4*)&b[4] = *(const float4*)&Bs[k][tx * 8 + 4];
#pragma unroll
      for (int i = 0; i < 8; i++)
#pragma unroll
        for (int j = 0; j < 8; j++) acc[i][j] += a[i] * b[j];
    }
    __syncthreads();
  }
#pragma unroll
  for (int i = 0; i < 8; i++) {
    int m = m0 + ty * 8 + i;
#pragma unroll
    for (int j = 0; j < 8; j++) {
      int n = n0 + tx * 8 + j;
      g_qh[(size_t)m * 1024 + n] = acc[i][j] + bias[n];
    }
  }
}

// ======================= scores ==============================================
__global__ __launch_bounds__(256) void scores_kernel(const float* __restrict__ keys) {
  int nt = blockIdx.x, h = blockIdx.y;
  __shared__ float q[128];
  __shared__ float ks[64 * 65];
  int tid = threadIdx.x;
  if (tid < 128) q[tid] = g_qh[((size_t)nt * NHEAD + h) * 128 + tid];
  __syncthreads();
  for (int half = 0; half < 2; half++) {
    const float* qhp = q + half * 64;
    float* dst = (half == 0) ? g_s1 : g_s2;
    for (int et = 0; et < 4; et++) {
      const float* kp = keys + ((size_t)(h * 2 + half) * 256 + et * 64) * 64;
      for (int idx = tid; idx < 4096; idx += 256) {
        int r = idx >> 6, c = idx & 63;
        ks[r * 65 + c] = kp[idx];
      }
      __syncthreads();
      int el = tid >> 2, qq = tid & 3;
      float sum = 0.f;
#pragma unroll
      for (int c = 0; c < 16; c++)
        sum += qhp[qq * 16 + c] * ks[el * 65 + qq * 16 + c];
      sum += __shfl_xor_sync(0xffffffffu, sum, 1);
      sum += __shfl_xor_sync(0xffffffffu, sum, 2);
      if (qq == 0)
        dst[((size_t)nt * NHEAD + h) * EXP + et * 64 + el] = sum;
      __syncthreads();
    }
  }
}

// ======================= warp-level top-k ====================================
__device__ __forceinline__ void warp_top16(float v[8], int lid, float& mv, int& mi) {
  for (int k = 0; k < KSEL; k++) {
    float bv = v[0];
    int br = 0;
#pragma unroll
    for (int r = 1; r < 8; r++)
      if (v[r] > bv) { bv = v[r]; br = r; }
    int code = br * 32 + lid;
#pragma unroll
    for (int off = 16; off; off >>= 1) {
      float ov = __shfl_xor_sync(0xffffffffu, bv, off);
      int oc = __shfl_xor_sync(0xffffffffu, code, off);
      if (ov > bv || (ov == bv && oc < code)) { bv = ov; code = oc; }
    }
    if (lid == k) { mv = bv; mi = code; }
    int owner = code & 31, reg = code >> 5;
    if (lid == owner) {
#pragma unroll
      for (int r = 0; r < 8; r++)
        if (r == reg) v[r] = -INFINITY;
    }
  }
}

__global__ __launch_bounds__(256) void topk_kernel() {
  int lid = threadIdx.x & 31;
  int w = threadIdx.x >> 5;
  int row = blockIdx.x * 8 + w;
  float v[8];
  float m1v = 0.f, m2v = 0.f, m3v = 0.f;
  int m1i = 0, m2i = 0, m3i = 0;

  const float* s1 = g_s1 + (size_t)row * EXP;
#pragma unroll
  for (int r = 0; r < 8; r++) v[r] = s1[r * 32 + lid];
  warp_top16(v, lid, m1v, m1i);

  const float* s2 = g_s2 + (size_t)row * EXP;
#pragma unroll
  for (int r = 0; r < 8; r++) v[r] = s2[r * 32 + lid];
  warp_top16(v, lid, m2v, m2i);

#pragma unroll
  for (int r = 0; r < 8; r++) {
    int t = r * 32 + lid;
    float a = __shfl_sync(0xffffffffu, m1v, t >> 4);
    float b = __shfl_sync(0xffffffffu, m2v, t & 15);
    v[r] = a + b;
  }
  warp_top16(v, lid, m3v, m3i);

  float mx = __shfl_sync(0xffffffffu, m3v, 0);
  float p = (lid < 16) ? expf(m3v - mx) : 0.f;
  float sum = p;
#pragma unroll
  for (int off = 16; off; off >>= 1) sum += __shfl_xor_sync(0xffffffffu, sum, off);
  float inv = 1.0f / sum;
  int i1 = __shfl_sync(0xffffffffu, m1i, (m3i >> 4) & 15);
  int i2 = __shfl_sync(0xffffffffu, m2i, m3i & 15);
  if (lid < 16) atomicAdd(&g_P[i1 * EXP + i2], p * inv);
}

// ======================= HMMA mainloop (fp16, 2-term) =========================
// CTA 128(M) x 256(N), 8 warps (2m x 4n), warp tile 64x64. K-chunk = 32 (64B).
// 4-stage cp.async ring (128KB dynamic smem). (Ah + Al) * B accumulation.
// 64B-row swizzle: seg' = seg ^ ((row>>1)&3) -> conflict-free ldsm + STS.
#define BM 128
#define BN 256
#define SM_AH 0
#define SM_AL 8192
#define SM_B  16384
#define STAGE_BYTES 32768
#define NSTAGE 4
#define DSMEM_SZ (NSTAGE * STAGE_BYTES)

__device__ __forceinline__ uint32_t swz(int row, int seg) {
  return (uint32_t)(row * 64 + ((seg ^ ((row >> 1) & 3)) << 4));
}

__device__ __forceinline__ void issue_chunk(
    uint32_t smb, int stage, const char* Ah, const char* Al,
    const char* B, size_t sA, size_t sB, int ck, int tid) {
  uint32_t base = smb + stage * STAGE_BYTES;
  size_t ko = (size_t)ck * 64;
#pragma unroll
  for (int t = 0; t < 2; t++) {
    int q = tid + t * 256;
    int row = q >> 2, seg = q & 3;
    uint32_t d = base + swz(row, seg);
    size_t so = (size_t)row * sA + ko + seg * 16;
    cp16(d + SM_AH, Ah + so);
    cp16(d + SM_AL, Al + so);
  }
#pragma unroll
  for (int t = 0; t < 4; t++) {
    int q = tid + t * 256;
    int row = q >> 2, seg = q & 3;
    uint32_t d = base + swz(row, seg);
    cp16(d + SM_B, B + (size_t)row * sB + ko + seg * 16);
  }
  CP_COMMIT;
}

__device__ __forceinline__ void mainloop3(
    const char* Ah, const char* Al, const char* B,
    size_t sA, size_t sB, int NC, float acc[4][8][4], char* sm) {
  uint32_t smb = (uint32_t)__cvta_generic_to_shared(sm);
  int tid = threadIdx.x, lane = tid & 31, wid = tid >> 5;
  int wm = (wid & 1) * 64, wn = (wid >> 1) * 64;
  int arow = ((lane >> 3) & 1) * 8 + (lane & 7);
  int aseg = lane >> 4;  // 0 or 1

  issue_chunk(smb, 0, Ah, Al, B, sA, sB, 0, tid);
  issue_chunk(smb, 1, Ah, Al, B, sA, sB, 1, tid);
  issue_chunk(smb, 2, Ah, Al, B, sA, sB, 2, tid);

  for (int ck = 0; ck < NC; ck++) {
    if (ck < NC - 2) { CP_WAIT2; }
    else if (ck == NC - 2) { CP_WAIT1; }
    else { CP_WAIT0; }
    __syncthreads();
    if (ck + 3 < NC)
      issue_chunk(smb, (ck + 3) % NSTAGE, Ah, Al, B, sA, sB, ck + 3, tid);
    uint32_t base = smb + (ck % NSTAGE) * STAGE_BYTES;
#pragma unroll
    for (int ks = 0; ks < 2; ks++) {
      int s = ks * 2 + aseg;
      uint32_t Af[4][4], Bf[4][4];
#pragma unroll
      for (int g = 0; g < 4; g++) {
        int row = wn + g * 16 + arow;
        ldsm4(Bf[g], base + SM_B + swz(row, s));
      }
#pragma unroll
      for (int mt = 0; mt < 4; mt++) {
        int row = wm + mt * 16 + arow;
        ldsm4(Af[mt], base + SM_AH + swz(row, s));
      }
#pragma unroll
      for (int mt = 0; mt < 4; mt++)
#pragma unroll
        for (int nt = 0; nt < 8; nt++) {
          int g = nt >> 1, j = nt & 1;
          mma16816(acc[mt][nt], Af[mt], Bf[g][j], Bf[g][j + 2]);
        }
#pragma unroll
      for (int mt = 0; mt < 4; mt++) {
        int row = wm + mt * 16 + arow;
        ldsm4(Af[mt], base + SM_AL + swz(row, s));
      }
#pragma unroll
      for (int mt = 0; mt < 4; mt++)
#pragma unroll
        for (int nt = 0; nt < 8; nt++) {
          int g = nt >> 1, j = nt & 1;
          mma16816(acc[mt][nt], Af[mt], Bf[g][j], Bf[g][j + 2]);
        }
    }
  }
}

// ---------- D1: S' = relu((Qh+Ql) @ Wdh^T) * P ; M=1024, N=65536, K=512 ------
__global__ __launch_bounds__(256, 1) void d1_kernel() {
  extern __shared__ __align__(1024) char dynsm[];
  int m0 = blockIdx.x * BM, n0 = blockIdx.y * BN;
  float acc[4][8][4];
#pragma unroll
  for (int a = 0; a < 4; a++)
#pragma unroll
    for (int c = 0; c < 8; c++)
#pragma unroll
      for (int d = 0; d < 4; d++) acc[a][c][d] = 0.f;

  mainloop3((const char*)(g_Qh + (size_t)m0 * 512),
            (const char*)(g_Ql + (size_t)m0 * 512),
            (const char*)(g_Wdh + (size_t)n0 * 512),
            1024, 1024, 16, acc, dynsm);

  int lane = threadIdx.x & 31, wid = threadIdx.x >> 5;
  int wm = (wid & 1) * 64, wn = (wid >> 1) * 64;
  int r0 = lane >> 2, cc = (lane & 3) * 2;
#pragma unroll
  for (int nt = 0; nt < 8; nt++) {
    int n = n0 + wn + nt * 8 + cc;
    float2 P2 = *(const float2*)&g_P[n];
#pragma unroll
    for (int mt = 0; mt < 4; mt++) {
#pragma unroll
      for (int h = 0; h < 2; h++) {
        int m = m0 + wm + mt * 16 + r0 + h * 8;
        float v0 = fmaxf(acc[mt][nt][2 * h + 0], 0.f) * P2.x;
        float v1 = fmaxf(acc[mt][nt][2 * h + 1], 0.f) * P2.y;
        uint32_t hw, lw;
        split2h(v0, v1, hw, lw);
        size_t o = (size_t)m * NE + n;
        *(uint32_t*)&g_Sh[o] = hw;
        *(uint32_t*)&g_Sl[o] = lw;
      }
    }
  }
}

// ---------- D2: out += (Sh+Sl) @ WuT^T ; M=1024, N=512, K=65536, splitK=32 ---
__global__ __launch_bounds__(256, 1) void d2_kernel(float* __restrict__ out) {
  extern __shared__ __align__(1024) char dynsm[];
  int m0 = blockIdx.x * BM;          // x fastest: 8 m-tiles share B chunk in L2
  int n0 = blockIdx.y * BN;          // 2 n-tiles
  size_t kb = (size_t)blockIdx.z * 4096;  // byte offset (2048 k-elems per split)
  float acc[4][8][4];
#pragma unroll
  for (int a = 0; a < 4; a++)
#pragma unroll
    for (int c = 0; c < 8; c++)
#pragma unroll
      for (int d = 0; d < 4; d++) acc[a][c][d] = 0.f;

  mainloop3((const char*)g_Sh + (size_t)m0 * 131072 + kb,
            (const char*)g_Sl + (size_t)m0 * 131072 + kb,
            (const char*)g_WuTh + (size_t)n0 * 131072 + kb,
            131072, 131072, 64, acc, dynsm);

  int lane = threadIdx.x & 31, wid = threadIdx.x >> 5;
  int wm = (wid & 1) * 64, wn = (wid >> 1) * 64;
  int r0 = lane >> 2, cc = (lane & 3) * 2;
#pragma unroll
  for (int nt = 0; nt < 8; nt++) {
    int n = n0 + wn + nt * 8 + cc;
#pragma unroll
    for (int mt = 0; mt < 4; mt++) {
#pragma unroll
      for (int h = 0; h < 2; h++) {
        int m = m0 + wm + mt * 16 + r0 + h * 8;
        atomicAdd(&out[(size_t)m * DIM + n], acc[mt][nt][2 * h + 0]);
        atomicAdd(&out[(size_t)m * DIM + n + 1], acc[mt][nt][2 * h + 1]);
      }
    }
  }
}

// ======================= launch ==============================================
extern "C" void kernel_launch(void* const* d_in, const int* in_sizes, int n_in,
                              void* d_out, int out_size) {
  const float* queries = (const float*)d_in[0];
  const float* Wq      = (const float*)d_in[1];
  const float* bq      = (const float*)d_in[2];
  const float* keys    = (const float*)d_in[3];
  const float* w_down  = (const float*)d_in[4];
  const float* w_up    = (const float*)d_in[5];
  float* out = (float*)d_out;

  cudaFuncSetAttribute(d1_kernel, cudaFuncAttributeMaxDynamicSharedMemorySize, DSMEM_SZ);
  cudaFuncSetAttribute(d2_kernel, cudaFuncAttributeMaxDynamicSharedMemorySize, DSMEM_SZ);

  zero_kernel<<<1024, 256>>>(out);
  split_q_kernel<<<256, 256>>>(queries);
  conv_wd_kernel<<<16384, 256>>>(w_down);
  trans_wu_kernel<<<dim3(2048, 16), dim3(32, 8)>>>(w_up);
  gemm_qh_kernel<<<dim3(8, 8), 256>>>(queries, Wq, bq);
  scores_kernel<<<dim3(1024, 8), 256>>>(keys);
  topk_kernel<<<1024, 256>>>();
  d1_kernel<<<dim3(8, 256), 256, DSMEM_SZ>>>();
  d2_kernel<<<dim3(8, 2, 32), 256, DSMEM_SZ>>>(out);
}

// round 7
// speedup vs baseline: 4.1312x; 1.4646x over previous
#include <cuda_runtime.h>
#include <cuda_fp16.h>
#include <cstdint>
#include <math.h>

#define NTOK 1024
#define DIM  512
#define NHEAD 8
#define EXP  256
#define NE   65536
#define KSEL 16

// ======================= device scratch ======================================
__device__ float g_qh[NTOK * NHEAD * 128];
__device__ float g_s1[NTOK * NHEAD * EXP];
__device__ float g_s2[NTOK * NHEAD * EXP];
__device__ float g_P[NE];
__device__ __align__(128) __half g_Qh[NTOK * DIM];
__device__ __align__(128) __half g_Wdh[(size_t)NE * DIM];    // 64 MB fp16
__device__ __align__(128) __half g_WuTh[(size_t)DIM * NE];   // 64 MB fp16
__device__ __align__(128) __half g_Sh[(size_t)NTOK * NE];    // 128 MB fp16

// ======================= small helpers =======================================
__device__ __forceinline__ void mma16816(float c[4], const uint32_t a[4],
                                         uint32_t b0, uint32_t b1) {
  asm volatile(
      "mma.sync.aligned.m16n8k16.row.col.f32.f16.f16.f32 "
      "{%0,%1,%2,%3}, {%4,%5,%6,%7}, {%8,%9}, {%0,%1,%2,%3};"
      : "+f"(c[0]), "+f"(c[1]), "+f"(c[2]), "+f"(c[3])
      : "r"(a[0]), "r"(a[1]), "r"(a[2]), "r"(a[3]), "r"(b0), "r"(b1));
}
__device__ __forceinline__ void ldsm4(uint32_t r[4], uint32_t addr) {
  asm volatile("ldmatrix.sync.aligned.m8n8.x4.shared.b16 {%0,%1,%2,%3}, [%4];"
               : "=r"(r[0]), "=r"(r[1]), "=r"(r[2]), "=r"(r[3]) : "r"(addr));
}
__device__ __forceinline__ void cp16(uint32_t dst, const void* src) {
  asm volatile("cp.async.cg.shared.global [%0], [%1], 16;" :: "r"(dst), "l"(src));
}
#define CP_COMMIT asm volatile("cp.async.commit_group;" ::: "memory")
#define CP_WAIT3  asm volatile("cp.async.wait_group 3;" ::: "memory")
#define CP_WAIT2  asm volatile("cp.async.wait_group 2;" ::: "memory")
#define CP_WAIT1  asm volatile("cp.async.wait_group 1;" ::: "memory")
#define CP_WAIT0  asm volatile("cp.async.wait_group 0;" ::: "memory")

// ======================= zero ================================================
__global__ void zero_kernel(float* __restrict__ out) {
  int i = blockIdx.x * blockDim.x + threadIdx.x;
  int stride = gridDim.x * blockDim.x;
  for (int j = i; j < NE; j += stride) g_P[j] = 0.f;
  for (int j = i; j < NTOK * DIM; j += stride) out[j] = 0.f;
}

// ======================= prep kernels ========================================
__device__ __forceinline__ uint32_t pack2h(float x0, float x1) {
  return (uint32_t)__half_as_ushort(__float2half(x0)) |
         ((uint32_t)__half_as_ushort(__float2half(x1)) << 16);
}

// fp32 -> fp16 (single), vectorized x8
__device__ __forceinline__ void conv_body(const float* __restrict__ src,
                                          __half* dst, int i) {
  const float4* s = (const float4*)src + (size_t)i * 2;
  float4 a = s[0], b = s[1];
  ((uint4*)dst)[i] = make_uint4(pack2h(a.x, a.y), pack2h(a.z, a.w),
                                pack2h(b.x, b.y), pack2h(b.z, b.w));
}
__global__ void conv_q_kernel(const float* __restrict__ src) {
  int i = blockIdx.x * blockDim.x + threadIdx.x;
  if (i < NTOK * DIM / 8) conv_body(src, g_Qh, i);
}
__global__ void conv_wd_kernel(const float* __restrict__ src) {
  int i = blockIdx.x * blockDim.x + threadIdx.x;
  if (i < (int)((size_t)NE * DIM / 8)) conv_body(src, g_Wdh, i);
}

// Wu [65536 x 512] fp32 -> WuT fp16 [512 x 65536] (transposed, single)
__global__ void trans_wu_kernel(const float* __restrict__ W) {
  __shared__ float t[32][33];
  int k0 = blockIdx.x * 32, n0 = blockIdx.y * 32;
  int tx = threadIdx.x, ty = threadIdx.y;
#pragma unroll
  for (int i = 0; i < 4; i++)
    t[ty + 8 * i][tx] = W[(size_t)(k0 + ty + 8 * i) * 512 + n0 + tx];
  __syncthreads();
#pragma unroll
  for (int i = 0; i < 4; i++) {
    float v = t[tx][ty + 8 * i];
    g_WuTh[(size_t)(n0 + ty + 8 * i) * NE + k0 + tx] = __float2half(v);
  }
}

// ======================= qh = Q @ Wq^T + bq (SIMT fp32) ======================
__global__ __launch_bounds__(256) void gemm_qh_kernel(
    const float* __restrict__ A, const float* __restrict__ B,
    const float* __restrict__ bias) {
  __shared__ float As[16][128];
  __shared__ float Bs[16][128];
  int m0 = blockIdx.x * 128, n0 = blockIdx.y * 128;
  int tid = threadIdx.x;
  int tx = tid & 15, ty = tid >> 4;
  int lr = tid >> 2, lc = tid & 3;
  float acc[8][8];
#pragma unroll
  for (int i = 0; i < 8; i++)
#pragma unroll
    for (int j = 0; j < 8; j++) acc[i][j] = 0.f;
  for (int k0 = 0; k0 < 512; k0 += 16) {
#pragma unroll
    for (int half = 0; half < 2; half++) {
      int r = lr + half * 64;
      float4 va = *(const float4*)&A[(size_t)(m0 + r) * 512 + k0 + lc * 4];
      As[lc * 4 + 0][r] = va.x; As[lc * 4 + 1][r] = va.y;
      As[lc * 4 + 2][r] = va.z; As[lc * 4 + 3][r] = va.w;
      float4 vb = *(const float4*)&B[(size_t)(n0 + r) * 512 + k0 + lc * 4];
      Bs[lc * 4 + 0][r] = vb.x; Bs[lc * 4 + 1][r] = vb.y;
      Bs[lc * 4 + 2][r] = vb.z; Bs[lc * 4 + 3][r] = vb.w;
    }
    __syncthreads();
#pragma unroll
    for (int k = 0; k < 16; k++) {
      float a[8], b[8];
      *(float4*)&a[0] = *(const float4*)&As[k][ty * 8];
      *(float4*)&a[4] = *(const float4*)&As[k][ty * 8 + 4];
      *(float4*)&b[0] = *(const float4*)&Bs[k][tx * 8];
      *(float4*)&b[4] = *(const float4*)&Bs[k][tx * 8 + 4];
#pragma unroll
      for (int i = 0; i < 8; i++)
#pragma unroll
        for (int j = 0; j < 8; j++) acc[i][j] += a[i] * b[j];
    }
    __syncthreads();
  }
#pragma unroll
  for (int i = 0; i < 8; i++) {
    int m = m0 + ty * 8 + i;
#pragma unroll
    for (int j = 0; j < 8; j++) {
      int n = n0 + tx * 8 + j;
      g_qh[(size_t)m * 1024 + n] = acc[i][j] + bias[n];
    }
  }
}

// ======================= scores ==============================================
__global__ __launch_bounds__(256) void scores_kernel(const float* __restrict__ keys) {
  int nt = blockIdx.x, h = blockIdx.y;
  __shared__ float q[128];
  __shared__ float ks[64 * 65];
  int tid = threadIdx.x;
  if (tid < 128) q[tid] = g_qh[((size_t)nt * NHEAD + h) * 128 + tid];
  __syncthreads();
  for (int half = 0; half < 2; half++) {
    const float* qhp = q + half * 64;
    float* dst = (half == 0) ? g_s1 : g_s2;
    for (int et = 0; et < 4; et++) {
      const float* kp = keys + ((size_t)(h * 2 + half) * 256 + et * 64) * 64;
      for (int idx = tid; idx < 4096; idx += 256) {
        int r = idx >> 6, c = idx & 63;
        ks[r * 65 + c] = kp[idx];
      }
      __syncthreads();
      int el = tid >> 2, qq = tid & 3;
      float sum = 0.f;
#pragma unroll
      for (int c = 0; c < 16; c++)
        sum += qhp[qq * 16 + c] * ks[el * 65 + qq * 16 + c];
      sum += __shfl_xor_sync(0xffffffffu, sum, 1);
      sum += __shfl_xor_sync(0xffffffffu, sum, 2);
      if (qq == 0)
        dst[((size_t)nt * NHEAD + h) * EXP + et * 64 + el] = sum;
      __syncthreads();
    }
  }
}

// ======================= warp-level top-k ====================================
__device__ __forceinline__ void warp_top16(float v[8], int lid, float& mv, int& mi) {
  for (int k = 0; k < KSEL; k++) {
    float bv = v[0];
    int br = 0;
#pragma unroll
    for (int r = 1; r < 8; r++)
      if (v[r] > bv) { bv = v[r]; br = r; }
    int code = br * 32 + lid;
#pragma unroll
    for (int off = 16; off; off >>= 1) {
      float ov = __shfl_xor_sync(0xffffffffu, bv, off);
      int oc = __shfl_xor_sync(0xffffffffu, code, off);
      if (ov > bv || (ov == bv && oc < code)) { bv = ov; code = oc; }
    }
    if (lid == k) { mv = bv; mi = code; }
    int owner = code & 31, reg = code >> 5;
    if (lid == owner) {
#pragma unroll
      for (int r = 0; r < 8; r++)
        if (r == reg) v[r] = -INFINITY;
    }
  }
}

__global__ __launch_bounds__(256) void topk_kernel() {
  int lid = threadIdx.x & 31;
  int w = threadIdx.x >> 5;
  int row = blockIdx.x * 8 + w;
  float v[8];
  float m1v = 0.f, m2v = 0.f, m3v = 0.f;
  int m1i = 0, m2i = 0, m3i = 0;

  const float* s1 = g_s1 + (size_t)row * EXP;
#pragma unroll
  for (int r = 0; r < 8; r++) v[r] = s1[r * 32 + lid];
  warp_top16(v, lid, m1v, m1i);

  const float* s2 = g_s2 + (size_t)row * EXP;
#pragma unroll
  for (int r = 0; r < 8; r++) v[r] = s2[r * 32 + lid];
  warp_top16(v, lid, m2v, m2i);

#pragma unroll
  for (int r = 0; r < 8; r++) {
    int t = r * 32 + lid;
    float a = __shfl_sync(0xffffffffu, m1v, t >> 4);
    float b = __shfl_sync(0xffffffffu, m2v, t & 15);
    v[r] = a + b;
  }
  warp_top16(v, lid, m3v, m3i);

  float mx = __shfl_sync(0xffffffffu, m3v, 0);
  float p = (lid < 16) ? expf(m3v - mx) : 0.f;
  float sum = p;
#pragma unroll
  for (int off = 16; off; off >>= 1) sum += __shfl_xor_sync(0xffffffffu, sum, off);
  float inv = 1.0f / sum;
  int i1 = __shfl_sync(0xffffffffu, m1i, (m3i >> 4) & 15);
  int i2 = __shfl_sync(0xffffffffu, m2i, m3i & 15);
  if (lid < 16) atomicAdd(&g_P[i1 * EXP + i2], p * inv);
}

// ======================= HMMA mainloop (fp16, 1-term) =========================
// CTA 128(M) x 256(N), 8 warps (2m x 4n), warp tile 64x64. K-chunk = 32 (64B).
// 5-stage cp.async ring (120KB dynamic smem), 4-deep prefetch.
// 64B-row swizzle: seg' = seg ^ ((row>>1)&3) -> conflict-free ldsm + STS.
#define BM 128
#define BN 256
#define SM_A 0
#define SM_B 8192
#define STAGE_BYTES 24576
#define NSTAGE 5
#define DSMEM_SZ (NSTAGE * STAGE_BYTES)

__device__ __forceinline__ uint32_t swz(int row, int seg) {
  return (uint32_t)(row * 64 + ((seg ^ ((row >> 1) & 3)) << 4));
}

__device__ __forceinline__ void issue_chunk(
    uint32_t smb, int stage, const char* A, const char* B,
    size_t sA, size_t sB, int ck, int tid) {
  uint32_t base = smb + stage * STAGE_BYTES;
  size_t ko = (size_t)ck * 64;
#pragma unroll
  for (int t = 0; t < 2; t++) {
    int q = tid + t * 256;
    int row = q >> 2, seg = q & 3;
    cp16(base + SM_A + swz(row, seg), A + (size_t)row * sA + ko + seg * 16);
  }
#pragma unroll
  for (int t = 0; t < 4; t++) {
    int q = tid + t * 256;
    int row = q >> 2, seg = q & 3;
    cp16(base + SM_B + swz(row, seg), B + (size_t)row * sB + ko + seg * 16);
  }
  CP_COMMIT;
}

__device__ __forceinline__ void mainloop1(
    const char* A, const char* B, size_t sA, size_t sB, int NC,
    float acc[4][8][4], char* sm) {
  uint32_t smb = (uint32_t)__cvta_generic_to_shared(sm);
  int tid = threadIdx.x, lane = tid & 31, wid = tid >> 5;
  int wm = (wid & 1) * 64, wn = (wid >> 1) * 64;
  int arow = ((lane >> 3) & 1) * 8 + (lane & 7);
  int aseg = lane >> 4;  // 0 or 1

  issue_chunk(smb, 0, A, B, sA, sB, 0, tid);
  issue_chunk(smb, 1, A, B, sA, sB, 1, tid);
  issue_chunk(smb, 2, A, B, sA, sB, 2, tid);
  issue_chunk(smb, 3, A, B, sA, sB, 3, tid);

  for (int ck = 0; ck < NC; ck++) {
    int infl = NC - 1 - ck;
    if (infl >= 3) { CP_WAIT3; }
    else if (infl == 2) { CP_WAIT2; }
    else if (infl == 1) { CP_WAIT1; }
    else { CP_WAIT0; }
    __syncthreads();
    if (ck + 4 < NC)
      issue_chunk(smb, (ck + 4) % NSTAGE, A, B, sA, sB, ck + 4, tid);
    uint32_t base = smb + (ck % NSTAGE) * STAGE_BYTES;
#pragma unroll
    for (int ks = 0; ks < 2; ks++) {
      int s = ks * 2 + aseg;
      uint32_t Af[4][4], Bf[4][4];
#pragma unroll
      for (int g = 0; g < 4; g++) {
        int row = wn + g * 16 + arow;
        ldsm4(Bf[g], base + SM_B + swz(row, s));
      }
#pragma unroll
      for (int mt = 0; mt < 4; mt++) {
        int row = wm + mt * 16 + arow;
        ldsm4(Af[mt], base + SM_A + swz(row, s));
      }
#pragma unroll
      for (int mt = 0; mt < 4; mt++)
#pragma unroll
        for (int nt = 0; nt < 8; nt++) {
          int g = nt >> 1, j = nt & 1;
          mma16816(acc[mt][nt], Af[mt], Bf[g][j], Bf[g][j + 2]);
        }
    }
  }
}

// ---------- D1: Sh = relu(Qh @ Wdh^T) * P ; M=1024, N=65536, K=512 -----------
__global__ __launch_bounds__(256, 1) void d1_kernel() {
  extern __shared__ __align__(1024) char dynsm[];
  int m0 = blockIdx.x * BM, n0 = blockIdx.y * BN;
  float acc[4][8][4];
#pragma unroll
  for (int a = 0; a < 4; a++)
#pragma unroll
    for (int c = 0; c < 8; c++)
#pragma unroll
      for (int d = 0; d < 4; d++) acc[a][c][d] = 0.f;

  mainloop1((const char*)(g_Qh + (size_t)m0 * 512),
            (const char*)(g_Wdh + (size_t)n0 * 512),
            1024, 1024, 16, acc, dynsm);

  int lane = threadIdx.x & 31, wid = threadIdx.x >> 5;
  int wm = (wid & 1) * 64, wn = (wid >> 1) * 64;
  int r0 = lane >> 2, cc = (lane & 3) * 2;
#pragma unroll
  for (int nt = 0; nt < 8; nt++) {
    int n = n0 + wn + nt * 8 + cc;
    float2 P2 = *(const float2*)&g_P[n];
#pragma unroll
    for (int mt = 0; mt < 4; mt++) {
#pragma unroll
      for (int h = 0; h < 2; h++) {
        int m = m0 + wm + mt * 16 + r0 + h * 8;
        float v0 = fmaxf(acc[mt][nt][2 * h + 0], 0.f) * P2.x;
        float v1 = fmaxf(acc[mt][nt][2 * h + 1], 0.f) * P2.y;
        *(uint32_t*)&g_Sh[(size_t)m * NE + n] = pack2h(v0, v1);
      }
    }
  }
}

// ---------- D2: out += Sh @ WuT^T ; M=1024, N=512, K=65536, splitK=32 --------
__global__ __launch_bounds__(256, 1) void d2_kernel(float* __restrict__ out) {
  extern __shared__ __align__(1024) char dynsm[];
  int m0 = blockIdx.x * BM;          // x fastest: 8 m-tiles share B chunk in L2
  int n0 = blockIdx.y * BN;          // 2 n-tiles
  size_t kb = (size_t)blockIdx.z * 4096;  // byte offset (2048 k-elems per split)
  float acc[4][8][4];
#pragma unroll
  for (int a = 0; a < 4; a++)
#pragma unroll
    for (int c = 0; c < 8; c++)
#pragma unroll
      for (int d = 0; d < 4; d++) acc[a][c][d] = 0.f;

  mainloop1((const char*)g_Sh + (size_t)m0 * 131072 + kb,
            (const char*)g_WuTh + (size_t)n0 * 131072 + kb,
            131072, 131072, 64, acc, dynsm);

  int lane = threadIdx.x & 31, wid = threadIdx.x >> 5;
  int wm = (wid & 1) * 64, wn = (wid >> 1) * 64;
  int r0 = lane >> 2, cc = (lane & 3) * 2;
#pragma unroll
  for (int nt = 0; nt < 8; nt++) {
    int n = n0 + wn + nt * 8 + cc;
#pragma unroll
    for (int mt = 0; mt < 4; mt++) {
#pragma unroll
      for (int h = 0; h < 2; h++) {
        int m = m0 + wm + mt * 16 + r0 + h * 8;
        atomicAdd(&out[(size_t)m * DIM + n], acc[mt][nt][2 * h + 0]);
        atomicAdd(&out[(size_t)m * DIM + n + 1], acc[mt][nt][2 * h + 1]);
      }
    }
  }
}

// ======================= launch ==============================================
extern "C" void kernel_launch(void* const* d_in, const int* in_sizes, int n_in,
                              void* d_out, int out_size) {
  const float* queries = (const float*)d_in[0];
  const float* Wq      = (const float*)d_in[1];
  const float* bq      = (const float*)d_in[2];
  const float* keys    = (const float*)d_in[3];
  const float* w_down  = (const float*)d_in[4];
  const float* w_up    = (const float*)d_in[5];
  float* out = (float*)d_out;

  cudaFuncSetAttribute(d1_kernel, cudaFuncAttributeMaxDynamicSharedMemorySize, DSMEM_SZ);
  cudaFuncSetAttribute(d2_kernel, cudaFuncAttributeMaxDynamicSharedMemorySize, DSMEM_SZ);

  zero_kernel<<<1024, 256>>>(out);
  conv_q_kernel<<<256, 256>>>(queries);
  conv_wd_kernel<<<16384, 256>>>(w_down);
  trans_wu_kernel<<<dim3(2048, 16), dim3(32, 8)>>>(w_up);
  gemm_qh_kernel<<<dim3(8, 8), 256>>>(queries, Wq, bq);
  scores_kernel<<<dim3(1024, 8), 256>>>(keys);
  topk_kernel<<<1024, 256>>>();
  d1_kernel<<<dim3(8, 256), 256, DSMEM_SZ>>>();
  d2_kernel<<<dim3(8, 2, 32), 256, DSMEM_SZ>>>(out);
}

// round 8
// speedup vs baseline: 4.5931x; 1.1118x over previous
#include <cuda_runtime.h>
#include <cuda_fp16.h>
#include <cstdint>
#include <math.h>

#define NTOK 1024
#define DIM  512
#define NHEAD 8
#define EXP  256
#define NE   65536
#define KSEL 16

// ======================= device scratch ======================================
__device__ float g_qh[NTOK * NHEAD * 128];
__device__ float g_s1[NTOK * NHEAD * EXP];
__device__ float g_s2[NTOK * NHEAD * EXP];
__device__ float g_P[NE];
__device__ __align__(128) __half g_Qh[NTOK * DIM];
__device__ __align__(128) __half g_Wdh[(size_t)NE * DIM];    // 64 MB fp16
__device__ __align__(128) __half g_WuTh[(size_t)DIM * NE];   // 64 MB fp16
__device__ __align__(128) __half g_Sh[(size_t)NTOK * NE];    // 128 MB fp16

// ======================= small helpers =======================================
__device__ __forceinline__ void mma16816(float c[4], const uint32_t a[4],
                                         uint32_t b0, uint32_t b1) {
  asm volatile(
      "mma.sync.aligned.m16n8k16.row.col.f32.f16.f16.f32 "
      "{%0,%1,%2,%3}, {%4,%5,%6,%7}, {%8,%9}, {%0,%1,%2,%3};"
      : "+f"(c[0]), "+f"(c[1]), "+f"(c[2]), "+f"(c[3])
      : "r"(a[0]), "r"(a[1]), "r"(a[2]), "r"(a[3]), "r"(b0), "r"(b1));
}
__device__ __forceinline__ void ldsm4(uint32_t r[4], uint32_t addr) {
  asm volatile("ldmatrix.sync.aligned.m8n8.x4.shared.b16 {%0,%1,%2,%3}, [%4];"
               : "=r"(r[0]), "=r"(r[1]), "=r"(r[2]), "=r"(r[3]) : "r"(addr));
}
__device__ __forceinline__ void cp16(uint32_t dst, const void* src) {
  asm volatile("cp.async.cg.shared.global [%0], [%1], 16;" :: "r"(dst), "l"(src));
}
#define CP_COMMIT asm volatile("cp.async.commit_group;" ::: "memory")
#define CP_WAIT3  asm volatile("cp.async.wait_group 3;" ::: "memory")
#define CP_WAIT2  asm volatile("cp.async.wait_group 2;" ::: "memory")
#define CP_WAIT1  asm volatile("cp.async.wait_group 1;" ::: "memory")
#define CP_WAIT0  asm volatile("cp.async.wait_group 0;" ::: "memory")

// ======================= zero ================================================
__global__ void zero_kernel(float* __restrict__ out) {
  int i = blockIdx.x * blockDim.x + threadIdx.x;
  int stride = gridDim.x * blockDim.x;
  for (int j = i; j < NE; j += stride) g_P[j] = 0.f;
  for (int j = i; j < NTOK * DIM; j += stride) out[j] = 0.f;
}

// ======================= prep kernels ========================================
__device__ __forceinline__ uint32_t pack2h(float x0, float x1) {
  return (uint32_t)__half_as_ushort(__float2half(x0)) |
         ((uint32_t)__half_as_ushort(__float2half(x1)) << 16);
}

__device__ __forceinline__ void conv_body(const float* __restrict__ src,
                                          __half* dst, int i) {
  const float4* s = (const float4*)src + (size_t)i * 2;
  float4 a = s[0], b = s[1];
  ((uint4*)dst)[i] = make_uint4(pack2h(a.x, a.y), pack2h(a.z, a.w),
                                pack2h(b.x, b.y), pack2h(b.z, b.w));
}
__global__ void conv_q_kernel(const float* __restrict__ src) {
  int i = blockIdx.x * blockDim.x + threadIdx.x;
  if (i < NTOK * DIM / 8) conv_body(src, g_Qh, i);
}
__global__ void conv_wd_kernel(const float* __restrict__ src) {
  int i = blockIdx.x * blockDim.x + threadIdx.x;
  if (i < (int)((size_t)NE * DIM / 8)) conv_body(src, g_Wdh, i);
}

// Wu [65536 x 512] fp32 -> WuT fp16 [512 x 65536] (transposed, single)
__global__ void trans_wu_kernel(const float* __restrict__ W) {
  __shared__ float t[32][33];
  int k0 = blockIdx.x * 32, n0 = blockIdx.y * 32;
  int tx = threadIdx.x, ty = threadIdx.y;
#pragma unroll
  for (int i = 0; i < 4; i++)
    t[ty + 8 * i][tx] = W[(size_t)(k0 + ty + 8 * i) * 512 + n0 + tx];
  __syncthreads();
#pragma unroll
  for (int i = 0; i < 4; i++) {
    float v = t[tx][ty + 8 * i];
    g_WuTh[(size_t)(n0 + ty + 8 * i) * NE + k0 + tx] = __float2half(v);
  }
}

// ======================= qh = Q @ Wq^T + bq (SIMT fp32) ======================
__global__ __launch_bounds__(256) void gemm_qh_kernel(
    const float* __restrict__ A, const float* __restrict__ B,
    const float* __restrict__ bias) {
  __shared__ float As[16][128];
  __shared__ float Bs[16][128];
  int m0 = blockIdx.x * 128, n0 = blockIdx.y * 128;
  int tid = threadIdx.x;
  int tx = tid & 15, ty = tid >> 4;
  int lr = tid >> 2, lc = tid & 3;
  float acc[8][8];
#pragma unroll
  for (int i = 0; i < 8; i++)
#pragma unroll
    for (int j = 0; j < 8; j++) acc[i][j] = 0.f;
  for (int k0 = 0; k0 < 512; k0 += 16) {
#pragma unroll
    for (int half = 0; half < 2; half++) {
      int r = lr + half * 64;
      float4 va = *(const float4*)&A[(size_t)(m0 + r) * 512 + k0 + lc * 4];
      As[lc * 4 + 0][r] = va.x; As[lc * 4 + 1][r] = va.y;
      As[lc * 4 + 2][r] = va.z; As[lc * 4 + 3][r] = va.w;
      float4 vb = *(const float4*)&B[(size_t)(n0 + r) * 512 + k0 + lc * 4];
      Bs[lc * 4 + 0][r] = vb.x; Bs[lc * 4 + 1][r] = vb.y;
      Bs[lc * 4 + 2][r] = vb.z; Bs[lc * 4 + 3][r] = vb.w;
    }
    __syncthreads();
#pragma unroll
    for (int k = 0; k < 16; k++) {
      float a[8], b[8];
      *(float4*)&a[0] = *(const float4*)&As[k][ty * 8];
      *(float4*)&a[4] = *(const float4*)&As[k][ty * 8 + 4];
      *(float4*)&b[0] = *(const float4*)&Bs[k][tx * 8];
      *(float4*)&b[4] = *(const float4*)&Bs[k][tx * 8 + 4];
#pragma unroll
      for (int i = 0; i < 8; i++)
#pragma unroll
        for (int j = 0; j < 8; j++) acc[i][j] += a[i] * b[j];
    }
    __syncthreads();
  }
#pragma unroll
  for (int i = 0; i < 8; i++) {
    int m = m0 + ty * 8 + i;
#pragma unroll
    for (int j = 0; j < 8; j++) {
      int n = n0 + tx * 8 + j;
      g_qh[(size_t)m * 1024 + n] = acc[i][j] + bias[n];
    }
  }
}

// ======================= scores ==============================================
__global__ __launch_bounds__(256) void scores_kernel(const float* __restrict__ keys) {
  int nt = blockIdx.x, h = blockIdx.y;
  __shared__ float q[128];
  __shared__ float ks[64 * 65];
  int tid = threadIdx.x;
  if (tid < 128) q[tid] = g_qh[((size_t)nt * NHEAD + h) * 128 + tid];
  __syncthreads();
  for (int half = 0; half < 2; half++) {
    const float* qhp = q + half * 64;
    float* dst = (half == 0) ? g_s1 : g_s2;
    for (int et = 0; et < 4; et++) {
      const float* kp = keys + ((size_t)(h * 2 + half) * 256 + et * 64) * 64;
      for (int idx = tid; idx < 4096; idx += 256) {
        int r = idx >> 6, c = idx & 63;
        ks[r * 65 + c] = kp[idx];
      }
      __syncthreads();
      int el = tid >> 2, qq = tid & 3;
      float sum = 0.f;
#pragma unroll
      for (int c = 0; c < 16; c++)
        sum += qhp[qq * 16 + c] * ks[el * 65 + qq * 16 + c];
      sum += __shfl_xor_sync(0xffffffffu, sum, 1);
      sum += __shfl_xor_sync(0xffffffffu, sum, 2);
      if (qq == 0)
        dst[((size_t)nt * NHEAD + h) * EXP + et * 64 + el] = sum;
      __syncthreads();
    }
  }
}

// ======================= warp-level top-k ====================================
__device__ __forceinline__ void warp_top16(float v[8], int lid, float& mv, int& mi) {
  for (int k = 0; k < KSEL; k++) {
    float bv = v[0];
    int br = 0;
#pragma unroll
    for (int r = 1; r < 8; r++)
      if (v[r] > bv) { bv = v[r]; br = r; }
    int code = br * 32 + lid;
#pragma unroll
    for (int off = 16; off; off >>= 1) {
      float ov = __shfl_xor_sync(0xffffffffu, bv, off);
      int oc = __shfl_xor_sync(0xffffffffu, code, off);
      if (ov > bv || (ov == bv && oc < code)) { bv = ov; code = oc; }
    }
    if (lid == k) { mv = bv; mi = code; }
    int owner = code & 31, reg = code >> 5;
    if (lid == owner) {
#pragma unroll
      for (int r = 0; r < 8; r++)
        if (r == reg) v[r] = -INFINITY;
    }
  }
}

__global__ __launch_bounds__(256) void topk_kernel() {
  int lid = threadIdx.x & 31;
  int w = threadIdx.x >> 5;
  int row = blockIdx.x * 8 + w;
  float v[8];
  float m1v = 0.f, m2v = 0.f, m3v = 0.f;
  int m1i = 0, m2i = 0, m3i = 0;

  const float* s1 = g_s1 + (size_t)row * EXP;
#pragma unroll
  for (int r = 0; r < 8; r++) v[r] = s1[r * 32 + lid];
  warp_top16(v, lid, m1v, m1i);

  const float* s2 = g_s2 + (size_t)row * EXP;
#pragma unroll
  for (int r = 0; r < 8; r++) v[r] = s2[r * 32 + lid];
  warp_top16(v, lid, m2v, m2i);

#pragma unroll
  for (int r = 0; r < 8; r++) {
    int t = r * 32 + lid;
    float a = __shfl_sync(0xffffffffu, m1v, t >> 4);
    float b = __shfl_sync(0xffffffffu, m2v, t & 15);
    v[r] = a + b;
  }
  warp_top16(v, lid, m3v, m3i);

  float mx = __shfl_sync(0xffffffffu, m3v, 0);
  float p = (lid < 16) ? expf(m3v - mx) : 0.f;
  float sum = p;
#pragma unroll
  for (int off = 16; off; off >>= 1) sum += __shfl_xor_sync(0xffffffffu, sum, off);
  float inv = 1.0f / sum;
  int i1 = __shfl_sync(0xffffffffu, m1i, (m3i >> 4) & 15);
  int i2 = __shfl_sync(0xffffffffu, m2i, m3i & 15);
  if (lid < 16) atomicAdd(&g_P[i1 * EXP + i2], p * inv);
}

// ======================= HMMA mainloop (fp16, 128x128, occ 2) =================
// CTA 128(M) x 128(N), 8 warps (2m x 4n), warp tile 64x32. K-chunk = 32 (64B).
// 5-stage cp.async ring (80KB dynamic smem), 4-deep prefetch, 2 CTAs/SM.
// 64B-row swizzle: seg' = seg ^ ((row>>1)&3) -> conflict-free ldsm + STS.
#define BM 128
#define BN 128
#define SM_A 0
#define SM_B 8192
#define STAGE_BYTES 16384
#define NSTAGE 5
#define DSMEM_SZ (NSTAGE * STAGE_BYTES)

__device__ __forceinline__ uint32_t swz(int row, int seg) {
  return (uint32_t)(row * 64 + ((seg ^ ((row >> 1) & 3)) << 4));
}

__device__ __forceinline__ void issue_chunk(
    uint32_t smb, int stage, const char* A, const char* B,
    size_t sA, size_t sB, int ck, int tid) {
  uint32_t base = smb + stage * STAGE_BYTES;
  size_t ko = (size_t)ck * 64;
#pragma unroll
  for (int t = 0; t < 2; t++) {
    int q = tid + t * 256;
    int row = q >> 2, seg = q & 3;
    cp16(base + SM_A + swz(row, seg), A + (size_t)row * sA + ko + seg * 16);
  }
#pragma unroll
  for (int t = 0; t < 2; t++) {
    int q = tid + t * 256;
    int row = q >> 2, seg = q & 3;
    cp16(base + SM_B + swz(row, seg), B + (size_t)row * sB + ko + seg * 16);
  }
  CP_COMMIT;
}

__device__ __forceinline__ void mainloop1(
    const char* A, const char* B, size_t sA, size_t sB, int NC,
    float acc[4][4][4], char* sm) {
  uint32_t smb = (uint32_t)__cvta_generic_to_shared(sm);
  int tid = threadIdx.x, lane = tid & 31, wid = tid >> 5;
  int wm = (wid & 1) * 64, wn = (wid >> 1) * 32;
  int arow = ((lane >> 3) & 1) * 8 + (lane & 7);
  int aseg = lane >> 4;  // 0 or 1

  issue_chunk(smb, 0, A, B, sA, sB, 0, tid);
  issue_chunk(smb, 1, A, B, sA, sB, 1, tid);
  issue_chunk(smb, 2, A, B, sA, sB, 2, tid);
  issue_chunk(smb, 3, A, B, sA, sB, 3, tid);

  for (int ck = 0; ck < NC; ck++) {
    int infl = NC - 1 - ck;
    if (infl >= 3) { CP_WAIT3; }
    else if (infl == 2) { CP_WAIT2; }
    else if (infl == 1) { CP_WAIT1; }
    else { CP_WAIT0; }
    __syncthreads();
    if (ck + 4 < NC)
      issue_chunk(smb, (ck + 4) % NSTAGE, A, B, sA, sB, ck + 4, tid);
    uint32_t base = smb + (ck % NSTAGE) * STAGE_BYTES;
#pragma unroll
    for (int ks = 0; ks < 2; ks++) {
      int s = ks * 2 + aseg;
      uint32_t Af[4][4], Bf[2][4];
#pragma unroll
      for (int g = 0; g < 2; g++) {
        int row = wn + g * 16 + arow;
        ldsm4(Bf[g], base + SM_B + swz(row, s));
      }
#pragma unroll
      for (int mt = 0; mt < 4; mt++) {
        int row = wm + mt * 16 + arow;
        ldsm4(Af[mt], base + SM_A + swz(row, s));
      }
#pragma unroll
      for (int mt = 0; mt < 4; mt++)
#pragma unroll
        for (int nt = 0; nt < 4; nt++) {
          int g = nt >> 1, j = nt & 1;
          mma16816(acc[mt][nt], Af[mt], Bf[g][j], Bf[g][j + 2]);
        }
    }
  }
}

// ---------- D1: Sh = relu(Qh @ Wdh^T) * P ; M=1024, N=65536, K=512 -----------
__global__ __launch_bounds__(256, 2) void d1_kernel() {
  extern __shared__ __align__(1024) char dynsm[];
  int m0 = blockIdx.x * BM, n0 = blockIdx.y * BN;
  float acc[4][4][4];
#pragma unroll
  for (int a = 0; a < 4; a++)
#pragma unroll
    for (int c = 0; c < 4; c++)
#pragma unroll
      for (int d = 0; d < 4; d++) acc[a][c][d] = 0.f;

  mainloop1((const char*)(g_Qh + (size_t)m0 * 512),
            (const char*)(g_Wdh + (size_t)n0 * 512),
            1024, 1024, 16, acc, dynsm);

  int lane = threadIdx.x & 31, wid = threadIdx.x >> 5;
  int wm = (wid & 1) * 64, wn = (wid >> 1) * 32;
  int r0 = lane >> 2, cc = (lane & 3) * 2;
#pragma unroll
  for (int nt = 0; nt < 4; nt++) {
    int n = n0 + wn + nt * 8 + cc;
    float2 P2 = *(const float2*)&g_P[n];
#pragma unroll
    for (int mt = 0; mt < 4; mt++) {
#pragma unroll
      for (int h = 0; h < 2; h++) {
        int m = m0 + wm + mt * 16 + r0 + h * 8;
        float v0 = fmaxf(acc[mt][nt][2 * h + 0], 0.f) * P2.x;
        float v1 = fmaxf(acc[mt][nt][2 * h + 1], 0.f) * P2.y;
        *(uint32_t*)&g_Sh[(size_t)m * NE + n] = pack2h(v0, v1);
      }
    }
  }
}

// ---------- D2: out += Sh @ WuT^T ; M=1024, N=512, K=65536, splitK=16 --------
__global__ __launch_bounds__(256, 2) void d2_kernel(float* __restrict__ out) {
  extern __shared__ __align__(1024) char dynsm[];
  int m0 = blockIdx.x * BM;          // x fastest: m-tiles share B chunk in L2
  int n0 = blockIdx.y * BN;          // 4 n-tiles
  size_t kb = (size_t)blockIdx.z * 8192;  // byte offset (4096 k-elems per split)
  float acc[4][4][4];
#pragma unroll
  for (int a = 0; a < 4; a++)
#pragma unroll
    for (int c = 0; c < 4; c++)
#pragma unroll
      for (int d = 0; d < 4; d++) acc[a][c][d] = 0.f;

  mainloop1((const char*)g_Sh + (size_t)m0 * 131072 + kb,
            (const char*)g_WuTh + (size_t)n0 * 131072 + kb,
            131072, 131072, 128, acc, dynsm);

  int lane = threadIdx.x & 31, wid = threadIdx.x >> 5;
  int wm = (wid & 1) * 64, wn = (wid >> 1) * 32;
  int r0 = lane >> 2, cc = (lane & 3) * 2;
#pragma unroll
  for (int nt = 0; nt < 4; nt++) {
    int n = n0 + wn + nt * 8 + cc;
#pragma unroll
    for (int mt = 0; mt < 4; mt++) {
#pragma unroll
      for (int h = 0; h < 2; h++) {
        int m = m0 + wm + mt * 16 + r0 + h * 8;
        atomicAdd(&out[(size_t)m * DIM + n], acc[mt][nt][2 * h + 0]);
        atomicAdd(&out[(size_t)m * DIM + n + 1], acc[mt][nt][2 * h + 1]);
      }
    }
  }
}

// ======================= launch ==============================================
extern "C" void kernel_launch(void* const* d_in, const int* in_sizes, int n_in,
                              void* d_out, int out_size) {
  const float* queries = (const float*)d_in[0];
  const float* Wq      = (const float*)d_in[1];
  const float* bq      = (const float*)d_in[2];
  const float* keys    = (const float*)d_in[3];
  const float* w_down  = (const float*)d_in[4];
  const float* w_up    = (const float*)d_in[5];
  float* out = (float*)d_out;

  cudaFuncSetAttribute(d1_kernel, cudaFuncAttributeMaxDynamicSharedMemorySize, DSMEM_SZ);
  cudaFuncSetAttribute(d2_kernel, cudaFuncAttributeMaxDynamicSharedMemorySize, DSMEM_SZ);

  zero_kernel<<<1024, 256>>>(out);
  conv_q_kernel<<<256, 256>>>(queries);
  conv_wd_kernel<<<16384, 256>>>(w_down);
  trans_wu_kernel<<<dim3(2048, 16), dim3(32, 8)>>>(w_up);
  gemm_qh_kernel<<<dim3(8, 8), 256>>>(queries, Wq, bq);
  scores_kernel<<<dim3(1024, 8), 256>>>(keys);
  topk_kernel<<<1024, 256>>>();
  d1_kernel<<<dim3(8, 512), 256, DSMEM_SZ>>>();
  d2_kernel<<<dim3(8, 4, 16), 256, DSMEM_SZ>>>(out);
}

// round 9
// speedup vs baseline: 5.1292x; 1.1167x over previous
#include <cuda_runtime.h>
#include <cuda_fp16.h>
#include <cstdint>
#include <math.h>

#define NTOK 1024
#define DIM  512
#define NHEAD 8
#define EXP  256
#define NE   65536
#define KSEL 16

// ======================= device scratch ======================================
__device__ float g_qh[NTOK * NHEAD * 128];
__device__ float g_s1[NTOK * NHEAD * EXP];
__device__ float g_s2[NTOK * NHEAD * EXP];
__device__ float g_P[NE];
__device__ __align__(128) __half g_Qh[NTOK * DIM];
__device__ __align__(128) __half g_Wdh[(size_t)NE * DIM];    // 64 MB fp16
__device__ __align__(128) __half g_WuTh[(size_t)DIM * NE];   // 64 MB fp16
__device__ __align__(128) __half g_Sh[(size_t)NTOK * NE];    // 128 MB fp16

// ======================= small helpers =======================================
__device__ __forceinline__ void mma16816(float c[4], const uint32_t a[4],
                                         uint32_t b0, uint32_t b1) {
  asm volatile(
      "mma.sync.aligned.m16n8k16.row.col.f32.f16.f16.f32 "
      "{%0,%1,%2,%3}, {%4,%5,%6,%7}, {%8,%9}, {%0,%1,%2,%3};"
      : "+f"(c[0]), "+f"(c[1]), "+f"(c[2]), "+f"(c[3])
      : "r"(a[0]), "r"(a[1]), "r"(a[2]), "r"(a[3]), "r"(b0), "r"(b1));
}
__device__ __forceinline__ void ldsm4(uint32_t r[4], uint32_t addr) {
  asm volatile("ldmatrix.sync.aligned.m8n8.x4.shared.b16 {%0,%1,%2,%3}, [%4];"
               : "=r"(r[0]), "=r"(r[1]), "=r"(r[2]), "=r"(r[3]) : "r"(addr));
}
__device__ __forceinline__ void cp16(uint32_t dst, const void* src) {
  asm volatile("cp.async.cg.shared.global [%0], [%1], 16;" :: "r"(dst), "l"(src));
}
#define CP_COMMIT asm volatile("cp.async.commit_group;" ::: "memory")
#define CP_WAIT1  asm volatile("cp.async.wait_group 1;" ::: "memory")
#define CP_WAIT0  asm volatile("cp.async.wait_group 0;" ::: "memory")

// ======================= zero ================================================
__global__ void zero_kernel(float* __restrict__ out) {
  int i = blockIdx.x * blockDim.x + threadIdx.x;
  int stride = gridDim.x * blockDim.x;
  for (int j = i; j < NE; j += stride) g_P[j] = 0.f;
  for (int j = i; j < NTOK * DIM; j += stride) out[j] = 0.f;
}

// ======================= prep kernels ========================================
__device__ __forceinline__ uint32_t pack2h(float x0, float x1) {
  return (uint32_t)__half_as_ushort(__float2half(x0)) |
         ((uint32_t)__half_as_ushort(__float2half(x1)) << 16);
}

__device__ __forceinline__ void conv_body(const float* __restrict__ src,
                                          __half* dst, int i) {
  const float4* s = (const float4*)src + (size_t)i * 2;
  float4 a = s[0], b = s[1];
  ((uint4*)dst)[i] = make_uint4(pack2h(a.x, a.y), pack2h(a.z, a.w),
                                pack2h(b.x, b.y), pack2h(b.z, b.w));
}
__global__ void conv_q_kernel(const float* __restrict__ src) {
  int i = blockIdx.x * blockDim.x + threadIdx.x;
  if (i < NTOK * DIM / 8) conv_body(src, g_Qh, i);
}
__global__ void conv_wd_kernel(const float* __restrict__ src) {
  int i = blockIdx.x * blockDim.x + threadIdx.x;
  if (i < (int)((size_t)NE * DIM / 8)) conv_body(src, g_Wdh, i);
}

// Wu [65536 x 512] fp32 -> WuT fp16 [512 x 65536] (transposed, single)
__global__ void trans_wu_kernel(const float* __restrict__ W) {
  __shared__ float t[32][33];
  int k0 = blockIdx.x * 32, n0 = blockIdx.y * 32;
  int tx = threadIdx.x, ty = threadIdx.y;
#pragma unroll
  for (int i = 0; i < 4; i++)
    t[ty + 8 * i][tx] = W[(size_t)(k0 + ty + 8 * i) * 512 + n0 + tx];
  __syncthreads();
#pragma unroll
  for (int i = 0; i < 4; i++) {
    float v = t[tx][ty + 8 * i];
    g_WuTh[(size_t)(n0 + ty + 8 * i) * NE + k0 + tx] = __float2half(v);
  }
}

// ======================= qh = Q @ Wq^T + bq (SIMT fp32, 64x64 tiles) =========
__global__ __launch_bounds__(256) void gemm_qh_kernel(
    const float* __restrict__ A, const float* __restrict__ B,
    const float* __restrict__ bias) {
  __shared__ float As[16][64];
  __shared__ float Bs[16][64];
  int m0 = blockIdx.x * 64, n0 = blockIdx.y * 64;
  int tid = threadIdx.x;
  int tx = tid & 15, ty = tid >> 4;
  int lr = tid >> 2, lc = tid & 3;
  float acc[4][4];
#pragma unroll
  for (int i = 0; i < 4; i++)
#pragma unroll
    for (int j = 0; j < 4; j++) acc[i][j] = 0.f;
  for (int k0 = 0; k0 < 512; k0 += 16) {
    float4 va = *(const float4*)&A[(size_t)(m0 + lr) * 512 + k0 + lc * 4];
    As[lc * 4 + 0][lr] = va.x; As[lc * 4 + 1][lr] = va.y;
    As[lc * 4 + 2][lr] = va.z; As[lc * 4 + 3][lr] = va.w;
    float4 vb = *(const float4*)&B[(size_t)(n0 + lr) * 512 + k0 + lc * 4];
    Bs[lc * 4 + 0][lr] = vb.x; Bs[lc * 4 + 1][lr] = vb.y;
    Bs[lc * 4 + 2][lr] = vb.z; Bs[lc * 4 + 3][lr] = vb.w;
    __syncthreads();
#pragma unroll
    for (int k = 0; k < 16; k++) {
      float a[4], b[4];
      *(float4*)&a[0] = *(const float4*)&As[k][ty * 4];
      *(float4*)&b[0] = *(const float4*)&Bs[k][tx * 4];
#pragma unroll
      for (int i = 0; i < 4; i++)
#pragma unroll
        for (int j = 0; j < 4; j++) acc[i][j] += a[i] * b[j];
    }
    __syncthreads();
  }
#pragma unroll
  for (int i = 0; i < 4; i++) {
    int m = m0 + ty * 4 + i;
#pragma unroll
    for (int j = 0; j < 4; j++) {
      int n = n0 + tx * 4 + j;
      g_qh[(size_t)m * 1024 + n] = acc[i][j] + bias[n];
    }
  }
}

// ======================= scores ==============================================
__global__ __launch_bounds__(256) void scores_kernel(const float* __restrict__ keys) {
  int nt = blockIdx.x, h = blockIdx.y;
  __shared__ float q[128];
  __shared__ float ks[64 * 65];
  int tid = threadIdx.x;
  if (tid < 128) q[tid] = g_qh[((size_t)nt * NHEAD + h) * 128 + tid];
  __syncthreads();
  for (int half = 0; half < 2; half++) {
    const float* qhp = q + half * 64;
    float* dst = (half == 0) ? g_s1 : g_s2;
    for (int et = 0; et < 4; et++) {
      const float* kp = keys + ((size_t)(h * 2 + half) * 256 + et * 64) * 64;
      for (int idx = tid; idx < 4096; idx += 256) {
        int r = idx >> 6, c = idx & 63;
        ks[r * 65 + c] = kp[idx];
      }
      __syncthreads();
      int el = tid >> 2, qq = tid & 3;
      float sum = 0.f;
#pragma unroll
      for (int c = 0; c < 16; c++)
        sum += qhp[qq * 16 + c] * ks[el * 65 + qq * 16 + c];
      sum += __shfl_xor_sync(0xffffffffu, sum, 1);
      sum += __shfl_xor_sync(0xffffffffu, sum, 2);
      if (qq == 0)
        dst[((size_t)nt * NHEAD + h) * EXP + et * 64 + el] = sum;
      __syncthreads();
    }
  }
}

// ======================= warp-level top-k ====================================
__device__ __forceinline__ void warp_top16(float v[8], int lid, float& mv, int& mi) {
  for (int k = 0; k < KSEL; k++) {
    float bv = v[0];
    int br = 0;
#pragma unroll
    for (int r = 1; r < 8; r++)
      if (v[r] > bv) { bv = v[r]; br = r; }
    int code = br * 32 + lid;
#pragma unroll
    for (int off = 16; off; off >>= 1) {
      float ov = __shfl_xor_sync(0xffffffffu, bv, off);
      int oc = __shfl_xor_sync(0xffffffffu, code, off);
      if (ov > bv || (ov == bv && oc < code)) { bv = ov; code = oc; }
    }
    if (lid == k) { mv = bv; mi = code; }
    int owner = code & 31, reg = code >> 5;
    if (lid == owner) {
#pragma unroll
      for (int r = 0; r < 8; r++)
        if (r == reg) v[r] = -INFINITY;
    }
  }
}

__global__ __launch_bounds__(256) void topk_kernel() {
  int lid = threadIdx.x & 31;
  int w = threadIdx.x >> 5;
  int row = blockIdx.x * 8 + w;
  float v[8];
  float m1v = 0.f, m2v = 0.f, m3v = 0.f;
  int m1i = 0, m2i = 0, m3i = 0;

  const float* s1 = g_s1 + (size_t)row * EXP;
#pragma unroll
  for (int r = 0; r < 8; r++) v[r] = s1[r * 32 + lid];
  warp_top16(v, lid, m1v, m1i);

  const float* s2 = g_s2 + (size_t)row * EXP;
#pragma unroll
  for (int r = 0; r < 8; r++) v[r] = s2[r * 32 + lid];
  warp_top16(v, lid, m2v, m2i);

#pragma unroll
  for (int r = 0; r < 8; r++) {
    int t = r * 32 + lid;
    float a = __shfl_sync(0xffffffffu, m1v, t >> 4);
    float b = __shfl_sync(0xffffffffu, m2v, t & 15);
    v[r] = a + b;
  }
  warp_top16(v, lid, m3v, m3i);

  float mx = __shfl_sync(0xffffffffu, m3v, 0);
  float p = (lid < 16) ? expf(m3v - mx) : 0.f;
  float sum = p;
#pragma unroll
  for (int off = 16; off; off >>= 1) sum += __shfl_xor_sync(0xffffffffu, sum, off);
  float inv = 1.0f / sum;
  int i1 = __shfl_sync(0xffffffffu, m1i, (m3i >> 4) & 15);
  int i2 = __shfl_sync(0xffffffffu, m2i, m3i & 15);
  if (lid < 16) atomicAdd(&g_P[i1 * EXP + i2], p * inv);
}

// ======================= HMMA mainloop (fp16, 128x128, BK=64, occ 2) ==========
// CTA 128(M) x 128(N), 8 warps (2m x 4n), warp tile 64x32. K-chunk = 64 (128B).
// 3-stage cp.async ring (96KB dynamic smem), 2-deep prefetch, 2 CTAs/SM.
// Canonical SW128 swizzle: seg' = seg ^ (row&7) -> conflict-free ldsm + STS.
#define BM 128
#define BN 128
#define SM_A 0
#define SM_B 16384
#define STAGE_BYTES 32768
#define NSTAGE 3
#define DSMEM_SZ (NSTAGE * STAGE_BYTES)

__device__ __forceinline__ uint32_t swz128(int row, int seg) {
  return (uint32_t)(row * 128 + ((seg ^ (row & 7)) << 4));
}

__device__ __forceinline__ void issue_chunk(
    uint32_t smb, int stage, const char* A, const char* B,
    size_t sA, size_t sB, int ck, int tid) {
  uint32_t base = smb + stage * STAGE_BYTES;
  size_t ko = (size_t)ck * 128;
#pragma unroll
  for (int t = 0; t < 4; t++) {
    int q = tid + t * 256;
    int row = q >> 3, seg = q & 7;
    cp16(base + SM_A + swz128(row, seg), A + (size_t)row * sA + ko + seg * 16);
  }
#pragma unroll
  for (int t = 0; t < 4; t++) {
    int q = tid + t * 256;
    int row = q >> 3, seg = q & 7;
    cp16(base + SM_B + swz128(row, seg), B + (size_t)row * sB + ko + seg * 16);
  }
  CP_COMMIT;
}

__device__ __forceinline__ void mainloop1(
    const char* A, const char* B, size_t sA, size_t sB, int NC,
    float acc[4][4][4], char* sm) {
  uint32_t smb = (uint32_t)__cvta_generic_to_shared(sm);
  int tid = threadIdx.x, lane = tid & 31, wid = tid >> 5;
  int wm = (wid & 1) * 64, wn = (wid >> 1) * 32;
  int arow = ((lane >> 3) & 1) * 8 + (lane & 7);
  int aseg = lane >> 4;  // 0 or 1 (16B half within the 32B k16 column)

  issue_chunk(smb, 0, A, B, sA, sB, 0, tid);
  issue_chunk(smb, 1, A, B, sA, sB, 1, tid);

  for (int ck = 0; ck < NC; ck++) {
    if (ck == NC - 1) { CP_WAIT0; } else { CP_WAIT1; }
    __syncthreads();
    if (ck + 2 < NC)
      issue_chunk(smb, (ck + 2) % NSTAGE, A, B, sA, sB, ck + 2, tid);
    uint32_t base = smb + (ck % NSTAGE) * STAGE_BYTES;
#pragma unroll
    for (int s = 0; s < 4; s++) {          // 4 k16 steps per 64-wide chunk
      int seg = s * 2 + aseg;
      uint32_t Af[4][4], Bf[2][4];
#pragma unroll
      for (int g = 0; g < 2; g++) {
        int row = wn + g * 16 + arow;
        ldsm4(Bf[g], base + SM_B + swz128(row, seg));
      }
#pragma unroll
      for (int mt = 0; mt < 4; mt++) {
        int row = wm + mt * 16 + arow;
        ldsm4(Af[mt], base + SM_A + swz128(row, seg));
      }
#pragma unroll
      for (int mt = 0; mt < 4; mt++)
#pragma unroll
        for (int nt = 0; nt < 4; nt++) {
          int g = nt >> 1, j = nt & 1;
          mma16816(acc[mt][nt], Af[mt], Bf[g][j], Bf[g][j + 2]);
        }
    }
  }
}

// ---------- D1: Sh = relu(Qh @ Wdh^T) * P ; M=1024, N=65536, K=512 -----------
__global__ __launch_bounds__(256, 2) void d1_kernel() {
  extern __shared__ __align__(1024) char dynsm[];
  int m0 = blockIdx.x * BM, n0 = blockIdx.y * BN;
  float acc[4][4][4];
#pragma unroll
  for (int a = 0; a < 4; a++)
#pragma unroll
    for (int c = 0; c < 4; c++)
#pragma unroll
      for (int d = 0; d < 4; d++) acc[a][c][d] = 0.f;

  mainloop1((const char*)(g_Qh + (size_t)m0 * 512),
            (const char*)(g_Wdh + (size_t)n0 * 512),
            1024, 1024, 8, acc, dynsm);

  int lane = threadIdx.x & 31, wid = threadIdx.x >> 5;
  int wm = (wid & 1) * 64, wn = (wid >> 1) * 32;
  int r0 = lane >> 2, cc = (lane & 3) * 2;
#pragma unroll
  for (int nt = 0; nt < 4; nt++) {
    int n = n0 + wn + nt * 8 + cc;
    float2 P2 = *(const float2*)&g_P[n];
#pragma unroll
    for (int mt = 0; mt < 4; mt++) {
#pragma unroll
      for (int h = 0; h < 2; h++) {
        int m = m0 + wm + mt * 16 + r0 + h * 8;
        float v0 = fmaxf(acc[mt][nt][2 * h + 0], 0.f) * P2.x;
        float v1 = fmaxf(acc[mt][nt][2 * h + 1], 0.f) * P2.y;
        *(uint32_t*)&g_Sh[(size_t)m * NE + n] = pack2h(v0, v1);
      }
    }
  }
}

// ---------- D2: out += Sh @ WuT^T ; M=1024, N=512, K=65536, splitK=18 --------
// 1024 chunks of 64 split unevenly: 16 z's get 57 chunks, 2 get 56.
__global__ __launch_bounds__(256, 2) void d2_kernel(float* __restrict__ out) {
  extern __shared__ __align__(1024) char dynsm[];
  int m0 = blockIdx.x * BM;          // x fastest: m-tiles share B chunk in L2
  int n0 = blockIdx.y * BN;          // 4 n-tiles
  int z = blockIdx.z;
  int start = z * 56 + (z < 16 ? z : 16);
  int cnt = 56 + (z < 16 ? 1 : 0);
  size_t kb = (size_t)start * 128;   // byte offset of this K partition
  float acc[4][4][4];
#pragma unroll
  for (int a = 0; a < 4; a++)
#pragma unroll
    for (int c = 0; c < 4; c++)
#pragma unroll
      for (int d = 0; d < 4; d++) acc[a][c][d] = 0.f;

  mainloop1((const char*)g_Sh + (size_t)m0 * 131072 + kb,
            (const char*)g_WuTh + (size_t)n0 * 131072 + kb,
            131072, 131072, cnt, acc, dynsm);

  int lane = threadIdx.x & 31, wid = threadIdx.x >> 5;
  int wm = (wid & 1) * 64, wn = (wid >> 1) * 32;
  int r0 = lane >> 2, cc = (lane & 3) * 2;
#pragma unroll
  for (int nt = 0; nt < 4; nt++) {
    int n = n0 + wn + nt * 8 + cc;
#pragma unroll
    for (int mt = 0; mt < 4; mt++) {
#pragma unroll
      for (int h = 0; h < 2; h++) {
        int m = m0 + wm + mt * 16 + r0 + h * 8;
        atomicAdd(&out[(size_t)m * DIM + n], acc[mt][nt][2 * h + 0]);
        atomicAdd(&out[(size_t)m * DIM + n + 1], acc[mt][nt][2 * h + 1]);
      }
    }
  }
}

// ======================= launch ==============================================
extern "C" void kernel_launch(void* const* d_in, const int* in_sizes, int n_in,
                              void* d_out, int out_size) {
  const float* queries = (const float*)d_in[0];
  const float* Wq      = (const float*)d_in[1];
  const float* bq      = (const float*)d_in[2];
  const float* keys    = (const float*)d_in[3];
  const float* w_down  = (const float*)d_in[4];
  const float* w_up    = (const float*)d_in[5];
  float* out = (float*)d_out;

  cudaFuncSetAttribute(d1_kernel, cudaFuncAttributeMaxDynamicSharedMemorySize, DSMEM_SZ);
  cudaFuncSetAttribute(d2_kernel, cudaFuncAttributeMaxDynamicSharedMemorySize, DSMEM_SZ);

  zero_kernel<<<1024, 256>>>(out);
  conv_q_kernel<<<256, 256>>>(queries);
  conv_wd_kernel<<<16384, 256>>>(w_down);
  trans_wu_kernel<<<dim3(2048, 16), dim3(32, 8)>>>(w_up);
  gemm_qh_kernel<<<dim3(16, 16), 256>>>(queries, Wq, bq);
  scores_kernel<<<dim3(1024, 8), 256>>>(keys);
  topk_kernel<<<1024, 256>>>();
  d1_kernel<<<dim3(8, 512), 256, DSMEM_SZ>>>();
  d2_kernel<<<dim3(8, 4, 18), 256, DSMEM_SZ>>>(out);
}